// round 7
// baseline (speedup 1.0000x reference)
#include <cuda_runtime.h>
#include <cuda_bf16.h>
#include <math.h>
#include <stdint.h>

#define B 128
#define S_SRC 128
#define S_TRG 64
#define H 1024
#define KSE 320
#define KAE 576
#define ECH 16
#define DCH 21
#define ACH 9216
#define ACH_B 18432
#define WCH 2304
#define WCH_B 4608
#define STG_B (2*ACH_B+WCH_B)
#define ENC_SMEM (ECH*WCH_B + 3*STG_B)
#define DEC_SMEM (DCH*WCH_B + 3*STG_B)
#define GEN_SMEM 92160

// chunked recurrent weights [nblk][c][32][72] (hi resident, lo streamed)
__device__ __align__(128) __nv_bfloat16 g_WerHc[128*ECH*WCH], g_WerLc[128*ECH*WCH];
__device__ __align__(128) __nv_bfloat16 g_WdrHc[128*DCH*WCH], g_WdrLc[128*DCH*WCH];
__device__ __align__(128) __nv_bfloat16 g_WaHc[14*16*576], g_WaLc[14*16*576];
// plain weights for one-shot GEMMs
__device__ __nv_bfloat16 g_WeiH[4096*KSE], g_WeiL[4096*KSE];
__device__ __nv_bfloat16 g_WdiH[4096*KAE], g_WdiL[4096*KAE];
__device__ __nv_bfloat16 g_WqkH[128*1024], g_WqkL[128*1024];
__device__ __nv_bfloat16 g_WqvH[320*1024], g_WqvL[320*1024];
__device__ __nv_bfloat16 g_Wh1H[2048*1024], g_Wh1L[2048*1024];
__device__ __nv_bfloat16 g_Wh2H[1024*2048], g_Wh2L[1024*2048];
__device__ __nv_bfloat16 g_Wc1H[2048*1024], g_Wc1L[2048*1024];
__device__ __nv_bfloat16 g_Wc2H[1024*2048], g_Wc2L[1024*2048];
// activations / state
__device__ __nv_bfloat16 g_seH[(size_t)S_SRC*B*KSE], g_seL[(size_t)S_SRC*B*KSE];
__device__ __nv_bfloat16 g_aeH[(size_t)S_TRG*B*KAE], g_aeL[(size_t)S_TRG*B*KAE];
__device__ float g_encpre[(size_t)S_SRC*B*4096];
__device__ float g_decpre[(size_t)S_TRG*B*4096];
__device__ __nv_bfloat16 g_shH[(size_t)B*S_SRC*H], g_shL[(size_t)B*S_SRC*H];
__device__ float g_qkey[(size_t)B*S_SRC*112];
__device__ float g_qval[(size_t)B*S_SRC*304];
__device__ __align__(128) __nv_bfloat16 g_ehT[2][2][ECH*ACH];   // chunked h [c][b][72]
__device__ __align__(128) __nv_bfloat16 g_dAT[2][2][DCH*ACH];
__device__ __nv_bfloat16 g_ehH[B*H], g_ehL[B*H];                // row-major final hT
__device__ float g_ec[B*H], g_dc[B*H];
__device__ __nv_bfloat16 g_ecH[B*H], g_ecL[B*H];
__device__ __nv_bfloat16 g_t1H[B*2048], g_t1L[B*2048];
__device__ float g_akey[B*112];
__device__ unsigned g_bar1, g_bar2;

#define CP_COMMIT asm volatile("cp.async.commit_group;" ::: "memory")
#define CP_WAIT0  asm volatile("cp.async.wait_group 0;" ::: "memory")
#define CP_WAIT1  asm volatile("cp.async.wait_group 1;" ::: "memory")
#define FENCEA    asm volatile("fence.proxy.async;" ::: "memory")

__device__ __forceinline__ void ldmx4(uint32_t a, uint32_t* r) {
    asm volatile("ldmatrix.sync.aligned.m8n8.x4.shared.b16 {%0,%1,%2,%3}, [%4];"
                 : "=r"(r[0]),"=r"(r[1]),"=r"(r[2]),"=r"(r[3]) : "r"(a));
}
__device__ __forceinline__ void ldmx2(uint32_t a, uint32_t* r) {
    asm volatile("ldmatrix.sync.aligned.m8n8.x2.shared.b16 {%0,%1}, [%2];"
                 : "=r"(r[0]),"=r"(r[1]) : "r"(a));
}
__device__ __forceinline__ void mma16816(float* c, const uint32_t* a, const uint32_t* b) {
    asm volatile("mma.sync.aligned.m16n8k16.row.col.f32.bf16.bf16.f32 "
                 "{%0,%1,%2,%3},{%4,%5,%6,%7},{%8,%9},{%0,%1,%2,%3};"
                 : "+f"(c[0]),"+f"(c[1]),"+f"(c[2]),"+f"(c[3])
                 : "r"(a[0]),"r"(a[1]),"r"(a[2]),"r"(a[3]),"r"(b[0]),"r"(b[1]));
}
__device__ __forceinline__ void cpa16(uint32_t d, const void* s) {
    asm volatile("cp.async.cg.shared.global [%0], [%1], 16;" :: "r"(d),"l"(s));
}
__device__ __forceinline__ void bulkcp(uint32_t d, const void* s, uint32_t n, uint32_t mb) {
    asm volatile("cp.async.bulk.shared::cluster.global.mbarrier::complete_tx::bytes [%0], [%1], %2, [%3];"
                 :: "r"(d),"l"(s),"r"(n),"r"(mb) : "memory");
}
__device__ __forceinline__ void mbar_init(uint32_t a, uint32_t c) {
    asm volatile("mbarrier.init.shared.b64 [%0], %1;" :: "r"(a),"r"(c) : "memory");
}
__device__ __forceinline__ void mbar_expect(uint32_t a, uint32_t b) {
    asm volatile("mbarrier.arrive.expect_tx.shared.b64 _, [%0], %1;" :: "r"(a),"r"(b) : "memory");
}
__device__ __forceinline__ void mbar_wait(uint32_t a, int p) {
    asm volatile("{\n\t.reg .pred P;\n\tWL_%=:\n\t"
                 "mbarrier.try_wait.parity.acquire.cta.shared::cta.b64 P, [%0], %1, 0x989680;\n\t"
                 "@P bra.uni WD_%=;\n\tbra.uni WL_%=;\n\tWD_%=:\n\t}"
                 :: "r"(a),"r"(p) : "memory");
}
__device__ __forceinline__ void grid_sync(unsigned* bar, unsigned target) {
    __syncthreads();
    if (threadIdx.x == 0) {
        __threadfence();
        atomicAdd(bar, 1u);
        volatile unsigned* vb = (volatile unsigned*)bar;
        while (*vb < target) __nanosleep(64);
        __threadfence();
    }
    __syncthreads();
}

// ---- setup: plain (mode 0) / packed-n (mode 1) row-major conversion ----
__global__ void convw_kernel(__nv_bfloat16* dh, __nv_bfloat16* dl, const float* __restrict__ s1,
                             int Npad, int Nreal, int Kpad, int Kreal, int lds, int mode) {
    int64_t tot = (int64_t)Npad * Kpad;
    int64_t stride = (int64_t)gridDim.x * blockDim.x;
    for (int64_t i = (int64_t)blockIdx.x*blockDim.x + threadIdx.x; i < tot; i += stride) {
        int n = (int)(i / Kpad), k = (int)(i % Kpad);
        float v = 0.f;
        if (mode == 0) { if (n < Nreal && k < Kreal) v = s1[(int64_t)n*lds + k]; }
        else { int orig = (n & 3)*1024 + (n >> 2); if (k < Kreal) v = s1[(int64_t)orig*lds + k]; }
        __nv_bfloat16 hv = __float2bfloat16(v);
        dh[i] = hv;
        dl[i] = __float2bfloat16(v - __bfloat162float(hv));
    }
}

// ---- setup: chunked weights [nblk][c][R][72]. mode1 enc packed, mode2 dec packed, mode3 Wa plain ----
__global__ void convwc_kernel(__nv_bfloat16* dh, __nv_bfloat16* dl,
                              const float* __restrict__ s1, const float* __restrict__ s2,
                              int nch, int nblkcnt, int R, int Kreal, int mode) {
    int64_t tot = (int64_t)nblkcnt * nch * R * 72;
    int64_t stride = (int64_t)gridDim.x * blockDim.x;
    for (int64_t i = (int64_t)blockIdx.x*blockDim.x + threadIdx.x; i < tot; i += stride) {
        int kk = (int)(i % 72);
        int r  = (int)((i / 72) % R);
        int c  = (int)((i / (72*R)) % nch);
        int nblk = (int)(i / ((int64_t)72*R*nch));
        int n = nblk*R + r, k = c*64 + kk;
        float v = 0.f;
        if (kk < 64 && k < Kreal) {
            if (mode == 3) { if (n < 100) v = s1[(int64_t)n*1024 + k]; }
            else {
                int orig = (n & 3)*1024 + (n >> 2);
                if (mode == 1) v = s1[(int64_t)orig*1024 + k];
                else v = (k < 1024) ? s1[(int64_t)orig*1024 + k]
                       : s2[(int64_t)orig*856 + 556 + (k - 1024)];
            }
        }
        __nv_bfloat16 hv = __float2bfloat16(v);
        dh[i] = hv;
        dl[i] = __float2bfloat16(v - __bfloat162float(hv));
    }
}

// ---- gather + zero init ----
__global__ void gather_kernel(const int* __restrict__ src_seqs, const int* __restrict__ trg_nt,
                              const int* __restrict__ par_nt, const int* __restrict__ par_lex,
                              const float* __restrict__ lex_emb, const float* __restrict__ nt_emb) {
    if (blockIdx.x == 0 && threadIdx.x == 0) { g_bar1 = 0u; g_bar2 = 0u; }
    const int64_t nse = (int64_t)S_SRC*B*KSE;
    const int64_t nae = (int64_t)S_TRG*B*KAE;
    const int64_t neh = 2LL*2*ECH*ACH, nda = 2LL*2*DCH*ACH;
    int64_t stride = (int64_t)gridDim.x * blockDim.x;
    __nv_bfloat16 z16 = __float2bfloat16(0.f);
    for (int64_t i = (int64_t)blockIdx.x*blockDim.x + threadIdx.x; i < nse; i += stride) {
        {
            int d = (int)(i % KSE), r = (int)(i / KSE);
            int s = r >> 7, b = r & 127;
            float v = (d < 300) ? lex_emb[(int64_t)src_seqs[b*S_SRC+s]*300 + d] : 0.f;
            __nv_bfloat16 hv = __float2bfloat16(v);
            g_seH[i] = hv; g_seL[i] = __float2bfloat16(v - __bfloat162float(hv));
        }
        if (i < nae) {
            int d = (int)(i % KAE), r = (int)(i / KAE);
            int t = r >> 7, b = r & 127;
            float v = 0.f;
            if (d < 128)      v = nt_emb[(int64_t)trg_nt[b*S_TRG+t]*128 + d];
            else if (d < 256) v = nt_emb[(int64_t)par_nt[b*S_TRG+t]*128 + (d-128)];
            else if (d < 556) v = lex_emb[(int64_t)par_lex[b*S_TRG+t]*300 + (d-256)];
            __nv_bfloat16 hv = __float2bfloat16(v);
            g_aeH[i] = hv; g_aeL[i] = __float2bfloat16(v - __bfloat162float(hv));
        }
        if (i < neh) ((__nv_bfloat16*)g_ehT)[i] = z16;
        if (i < nda) ((__nv_bfloat16*)g_dAT)[i] = z16;
        if (i < B*H) { g_ec[i] = 0.f; g_ehH[i] = z16; g_ehL[i] = z16; }
    }
}

// ---- MMA on one 64-wide K chunk (stage: Ahi rows0-127, Alo 128-255, Wlo 256-287; 72 stride) ----
__device__ __forceinline__ void mma_chunk(uint32_t smWc, uint32_t st,
    int lane, int wm, int wn, float acc[2][2][4]) {
#pragma unroll
    for (int kk16 = 0; kk16 < 64; kk16 += 16) {
        uint32_t bh[2][2], bl[2][2];
#pragma unroll
        for (int nf = 0; nf < 2; nf++) {
            int rowW = wn*16 + nf*8 + (lane & 7);
            int kcol = kk16 + ((lane >> 3) & 1)*8;
            ldmx2(smWc + (uint32_t)(rowW*72 + kcol)*2u, bh[nf]);
            ldmx2(st + 2*ACH_B + (uint32_t)(rowW*72 + kcol)*2u, bl[nf]);
        }
#pragma unroll
        for (int mf = 0; mf < 2; mf++) {
            int rowA = wm*32 + mf*16 + (lane & 7) + ((lane >> 3) & 1)*8;
            int kcol = kk16 + ((lane >> 4) & 1)*8;
            uint32_t ah[4], al[4];
            ldmx4(st + (uint32_t)(rowA*72 + kcol)*2u, ah);
            ldmx4(st + ACH_B + (uint32_t)(rowA*72 + kcol)*2u, al);
#pragma unroll
            for (int nf = 0; nf < 2; nf++) {
                mma16816(acc[mf][nf], ah, bh[nf]);
                mma16816(acc[mf][nf], al, bh[nf]);
                mma16816(acc[mf][nf], ah, bl[nf]);
            }
        }
    }
}

__device__ __forceinline__ void issue3(uint32_t st, uint32_t mbar,
    const __nv_bfloat16* ATh, const __nv_bfloat16* ATl, const __nv_bfloat16* Wlc, int c) {
    FENCEA;
    mbar_expect(mbar, (uint32_t)STG_B);
    bulkcp(st, ATh + (size_t)c*ACH, ACH_B, mbar);
    bulkcp(st + ACH_B, ATl + (size_t)c*ACH, ACH_B, mbar);
    bulkcp(st + 2*ACH_B, Wlc + (size_t)c*WCH, WCH_B, mbar);
}

template<int KCH>
__device__ __forceinline__ void gemm_bulk(uint32_t smW, uint32_t smS, uint32_t mb,
    int t, int lane, int wm, int wn, int* ph,
    const __nv_bfloat16* ATh, const __nv_bfloat16* ATl, const __nv_bfloat16* Wlc,
    float acc[2][2][4]) {
    if (t == 0) {
        issue3(smS, mb, ATh, ATl, Wlc, 0);
        issue3(smS + STG_B, mb + 8, ATh, ATl, Wlc, 1);
        issue3(smS + 2*STG_B, mb + 16, ATh, ATl, Wlc, 2);
    }
    for (int c = 0; c < KCH; c++) {
        int s = c % 3;
        mbar_wait(mb + s*8, ph[s]); ph[s] ^= 1;
        mma_chunk(smW + (uint32_t)c*WCH_B, smS + (uint32_t)s*STG_B, lane, wm, wn, acc);
        __syncthreads();
        if (t == 0 && c + 3 < KCH)
            issue3(smS + (uint32_t)s*STG_B, mb + s*8, ATh, ATl, Wlc, c + 3);
    }
}

// ---- persistent encoder ----
__global__ __launch_bounds__(256) void enc_persist(const float* __restrict__ biasv,
                                                   const int* __restrict__ lens) {
    extern __shared__ char smraw[];
    __shared__ __align__(8) unsigned long long s_mb[4];
    const uint32_t smb = (uint32_t)__cvta_generic_to_shared(smraw);
    const uint32_t smW = smb, smS = smb + (uint32_t)(ECH*WCH_B);
    const uint32_t mb = (uint32_t)__cvta_generic_to_shared(s_mb);
    const int t = threadIdx.x, lane = t & 31, w = t >> 5;
    const int wm = w & 3, wn = w >> 2;
    const int nblk = blockIdx.x;
    const int g2 = lane >> 2, q2 = (lane & 3)*2;

    if (t == 0) {
        for (int i = 0; i < 4; i++) mbar_init(mb + i*8, 1);
        FENCEA;
        mbar_expect(mb + 24, (uint32_t)(ECH*WCH_B));
        bulkcp(smW, g_WerHc + (size_t)nblk*ECH*WCH, ECH*WCH_B, mb + 24);
    }
    __syncthreads();
    mbar_wait(mb + 24, 0);

    const __nv_bfloat16* Wlc = g_WerLc + (size_t)nblk*ECH*WCH;
    int ph[3] = {0, 0, 0};
    unsigned target = 0;

    for (int s = 0; s < S_SRC; s++) {
        const int p = s & 1, q = p ^ 1;
        float acc[2][2][4];
#pragma unroll
        for (int a = 0; a < 2; a++)
#pragma unroll
            for (int b2 = 0; b2 < 2; b2++)
#pragma unroll
                for (int r = 0; r < 4; r++) acc[a][b2][r] = 0.f;

        gemm_bulk<ECH>(smW, smS, mb, t, lane, wm, wn, ph,
                       &g_ehT[p][0][0], &g_ehT[p][1][0], Wlc, acc);

        float* zb = (float*)(smraw + ECH*WCH_B);
#pragma unroll
        for (int mf = 0; mf < 2; mf++)
#pragma unroll
            for (int nf = 0; nf < 2; nf++)
#pragma unroll
                for (int r = 0; r < 4; r++)
                    zb[(wm*32 + mf*16 + g2 + (r >> 1)*8)*33 + wn*16 + nf*8 + q2 + (r & 1)] = acc[mf][nf][r];
        __syncthreads();

        const int b = t & 127;
        const int jj0 = (t >> 7)*4;
        const bool valid = s < lens[b];
        __nv_bfloat16 z16 = __float2bfloat16(0.f);
        const float* add = g_encpre + (int64_t)s*B*4096;
#pragma unroll
        for (int jj = jj0; jj < jj0 + 4; jj++) {
            int jglob = nblk*8 + jj;
            float4 pre = *(const float4*)&add[(int64_t)b*4096 + nblk*32 + jj*4];
            float zi = zb[b*33 + jj*4 + 0] + pre.x + biasv[jglob];
            float zf = zb[b*33 + jj*4 + 1] + pre.y + biasv[1024 + jglob];
            float zg = zb[b*33 + jj*4 + 2] + pre.z + biasv[2048 + jglob];
            float zo = zb[b*33 + jj*4 + 3] + pre.w + biasv[3072 + jglob];
            float cold = g_ec[b*H + jglob];
            float si = 1.f/(1.f + expf(-zi));
            float sf = 1.f/(1.f + expf(-zf));
            float so = 1.f/(1.f + expf(-zo));
            float c2 = sf*cold + si*tanhf(zg);
            float h2 = so*tanhf(c2);
            if (valid) g_ec[b*H + jglob] = c2;
            __nv_bfloat16 nh = __float2bfloat16(h2);
            __nv_bfloat16 nl = __float2bfloat16(h2 - __bfloat162float(nh));
            size_t tix = ((size_t)(jglob >> 6)*128 + b)*72 + (jglob & 63);
            __nv_bfloat16 oh = g_ehT[p][0][tix], ol = g_ehT[p][1][tix];
            g_ehT[q][0][tix] = valid ? nh : oh;
            g_ehT[q][1][tix] = valid ? nl : ol;
            if (valid) { g_ehH[b*H + jglob] = nh; g_ehL[b*H + jglob] = nl; }
            g_shH[((int64_t)b*S_SRC + s)*H + jglob] = valid ? nh : z16;
            g_shL[((int64_t)b*S_SRC + s)*H + jglob] = valid ? nl : z16;
        }
        grid_sync(&g_bar1, target += 128);
    }
}

// ---- persistent decoder ----
__global__ __launch_bounds__(256) void dec_persist(const float* __restrict__ biasv,
                                                   const float* __restrict__ ba_,
                                                   const int* __restrict__ lens,
                                                   float* __restrict__ outF) {
    extern __shared__ char smraw[];
    __shared__ __align__(8) unsigned long long s_mb[4];
    __shared__ float s_ak[112], s_en[128], s_red[8];
    const uint32_t smb = (uint32_t)__cvta_generic_to_shared(smraw);
    const uint32_t smW = smb, smS = smb + (uint32_t)(DCH*WCH_B);
    const uint32_t mb = (uint32_t)__cvta_generic_to_shared(s_mb);
    const int t = threadIdx.x, lane = t & 31, w = t >> 5;
    const int wm = w & 3, wn = w >> 2;
    const int nblk = blockIdx.x;
    const int g2 = lane >> 2, q2 = (lane & 3)*2;

    if (t == 0) {
        for (int i = 0; i < 4; i++) mbar_init(mb + i*8, 1);
        FENCEA;
        mbar_expect(mb + 24, (uint32_t)(DCH*WCH_B));
        bulkcp(smW, g_WdrHc + (size_t)nblk*DCH*WCH, DCH*WCH_B, mb + 24);
    }
    __syncthreads();
    mbar_wait(mb + 24, 0);

    const __nv_bfloat16* Wlc = g_WdrLc + (size_t)nblk*DCH*WCH;
    int ph[3] = {0, 0, 0};
    unsigned target = 0;

    for (int ts = 0; ts < S_TRG; ts++) {
        const int p = ts & 1, q = p ^ 1;
        const __nv_bfloat16* ATh = &g_dAT[p][0][0];
        const __nv_bfloat16* ATl = &g_dAT[p][1][0];

        // A1: a_key mini-GEMM (blocks 0..13, N=8, K=1024 chunks 0..15)
        if (nblk < 14) {
            float acm[4] = {0.f, 0.f, 0.f, 0.f};
            if (t == 0) {
#pragma unroll
                for (int c0 = 0; c0 < 3; c0++) {
                    uint32_t st = smS + (uint32_t)c0*STG_B;
                    FENCEA;
                    mbar_expect(mb + c0*8, 2u*ACH_B + 2304u);
                    bulkcp(st, ATh + (size_t)c0*ACH, ACH_B, mb + c0*8);
                    bulkcp(st + ACH_B, ATl + (size_t)c0*ACH, ACH_B, mb + c0*8);
                    bulkcp(st + 2*ACH_B, g_WaHc + (size_t)(nblk*16 + c0)*576, 1152u, mb + c0*8);
                    bulkcp(st + 2*ACH_B + 1152u, g_WaLc + (size_t)(nblk*16 + c0)*576, 1152u, mb + c0*8);
                }
            }
            for (int c = 0; c < 16; c++) {
                int s = c % 3;
                mbar_wait(mb + s*8, ph[s]); ph[s] ^= 1;
                uint32_t st = smS + (uint32_t)s*STG_B;
#pragma unroll
                for (int kk16 = 0; kk16 < 64; kk16 += 16) {
                    uint32_t bhp[2], blp[2];
                    int rowW = lane & 7;
                    int kcW = kk16 + ((lane >> 3) & 1)*8;
                    ldmx2(st + 2*ACH_B + (uint32_t)(rowW*72 + kcW)*2u, bhp);
                    ldmx2(st + 2*ACH_B + 1152u + (uint32_t)(rowW*72 + kcW)*2u, blp);
                    int rowA = w*16 + (lane & 7) + ((lane >> 3) & 1)*8;
                    int kcA = kk16 + ((lane >> 4) & 1)*8;
                    uint32_t ah[4], al[4];
                    ldmx4(st + (uint32_t)(rowA*72 + kcA)*2u, ah);
                    ldmx4(st + ACH_B + (uint32_t)(rowA*72 + kcA)*2u, al);
                    mma16816(acm, ah, bhp);
                    mma16816(acm, al, bhp);
                    mma16816(acm, ah, blp);
                }
                __syncthreads();
                if (t == 0 && c + 3 < 16) {
                    uint32_t st2 = smS + (uint32_t)s*STG_B;
                    int c3 = c + 3;
                    FENCEA;
                    mbar_expect(mb + s*8, 2u*ACH_B + 2304u);
                    bulkcp(st2, ATh + (size_t)c3*ACH, ACH_B, mb + s*8);
                    bulkcp(st2 + ACH_B, ATl + (size_t)c3*ACH, ACH_B, mb + s*8);
                    bulkcp(st2 + 2*ACH_B, g_WaHc + (size_t)(nblk*16 + c3)*576, 1152u, mb + s*8);
                    bulkcp(st2 + 2*ACH_B + 1152u, g_WaLc + (size_t)(nblk*16 + c3)*576, 1152u, mb + s*8);
                }
            }
#pragma unroll
            for (int r = 0; r < 4; r++) {
                int row = w*16 + g2 + (r >> 1)*8;
                int gc = nblk*8 + q2 + (r & 1);
                float bb = (gc < 100) ? ba_[gc] : 0.f;
                g_akey[row*112 + gc] = tanhf(acm[r] + bb);
            }
        }
        grid_sync(&g_bar2, target += 128);

        // A2: softmax + context for batch nblk (writes ctx chunks 16..20)
        {
            if (t < 112) s_ak[t] = g_akey[nblk*112 + t];
            __syncthreads();
            float ex = 0.f;
            if (t < 128) {
                int L = lens[nblk];
                const float* qk = g_qkey + ((int64_t)nblk*S_SRC + t)*112;
                float pp = 0.f;
#pragma unroll 4
                for (int d = 0; d < 100; d++) pp = fmaf(qk[d], s_ak[d], pp);
                float e = (t < L) ? pp : -1e9f;
                float mx = e;
                for (int o = 16; o; o >>= 1) mx = fmaxf(mx, __shfl_xor_sync(0xffffffffu, mx, o));
                if (lane == 0) s_red[w] = mx;
                s_en[t] = e;
            }
            __syncthreads();
            if (t < 128) {
                float mx = fmaxf(fmaxf(s_red[0], s_red[1]), fmaxf(s_red[2], s_red[3]));
                ex = expf(s_en[t] - mx);
                float sm = ex;
                for (int o = 16; o; o >>= 1) sm += __shfl_xor_sync(0xffffffffu, sm, o);
                if (lane == 0) s_red[4 + w] = sm;
            }
            __syncthreads();
            if (t < 128) s_en[t] = ex;
            __syncthreads();
            float denom = s_red[4] + s_red[5] + s_red[6] + s_red[7];
            for (int d = t; d < 300; d += 256) {
                float c = 0.f;
#pragma unroll 4
                for (int s2 = 0; s2 < S_SRC; s2++)
                    c = fmaf(s_en[s2], g_qval[((int64_t)nblk*S_SRC + s2)*304 + d], c);
                c /= denom;
                __nv_bfloat16 hv = __float2bfloat16(c);
                int kc = 1024 + d;
                size_t tix = ((size_t)(kc >> 6)*128 + nblk)*72 + (kc & 63);
                g_dAT[p][0][tix] = hv;
                g_dAT[p][1][tix] = __float2bfloat16(c - __bfloat162float(hv));
            }
        }
        grid_sync(&g_bar2, target += 128);

        // B: recurrent GEMM + LSTM epilogue
        {
            float acc[2][2][4];
#pragma unroll
            for (int a = 0; a < 2; a++)
#pragma unroll
                for (int b2 = 0; b2 < 2; b2++)
#pragma unroll
                    for (int r = 0; r < 4; r++) acc[a][b2][r] = 0.f;

            gemm_bulk<DCH>(smW, smS, mb, t, lane, wm, wn, ph, ATh, ATl, Wlc, acc);

            float* zb = (float*)(smraw + DCH*WCH_B);
#pragma unroll
            for (int mf = 0; mf < 2; mf++)
#pragma unroll
                for (int nf = 0; nf < 2; nf++)
#pragma unroll
                    for (int r = 0; r < 4; r++)
                        zb[(wm*32 + mf*16 + g2 + (r >> 1)*8)*33 + wn*16 + nf*8 + q2 + (r & 1)] = acc[mf][nf][r];
            __syncthreads();

            const int b = t & 127;
            const int jj0 = (t >> 7)*4;
            const float* add = g_decpre + (int64_t)ts*B*4096;
#pragma unroll
            for (int jj = jj0; jj < jj0 + 4; jj++) {
                int jglob = nblk*8 + jj;
                float4 pre = *(const float4*)&add[(int64_t)b*4096 + nblk*32 + jj*4];
                float zi = zb[b*33 + jj*4 + 0] + pre.x + biasv[jglob];
                float zf = zb[b*33 + jj*4 + 1] + pre.y + biasv[1024 + jglob];
                float zg = zb[b*33 + jj*4 + 2] + pre.z + biasv[2048 + jglob];
                float zo = zb[b*33 + jj*4 + 3] + pre.w + biasv[3072 + jglob];
                float cold = g_dc[b*H + jglob];
                float si = 1.f/(1.f + expf(-zi));
                float sf = 1.f/(1.f + expf(-zf));
                float so = 1.f/(1.f + expf(-zo));
                float c2 = sf*cold + si*tanhf(zg);
                float h2 = so*tanhf(c2);
                g_dc[b*H + jglob] = c2;
                __nv_bfloat16 nh = __float2bfloat16(h2);
                __nv_bfloat16 nl = __float2bfloat16(h2 - __bfloat162float(nh));
                size_t tix = ((size_t)(jglob >> 6)*128 + b)*72 + (jglob & 63);
                g_dAT[q][0][tix] = nh;
                g_dAT[q][1][tix] = nl;
                outF[((int64_t)b*S_TRG + ts)*H + jglob] = h2;
            }
        }
        grid_sync(&g_bar2, target += 128);
    }
}

// ---- one-shot GEMM (cp.async path; OUT: 0 fp32, 1 bf16 hi/lo, 2 bf16 chunked) ----
__device__ __forceinline__ void load_chunk_g(uint32_t smb, int buf, int t, int k0,
    const __nv_bfloat16* __restrict__ Ah, const __nv_bfloat16* __restrict__ Al, int ldA, int mbase,
    const __nv_bfloat16* __restrict__ Wh, const __nv_bfloat16* __restrict__ Wl, int ldW, int nbase) {
#pragma unroll
    for (int i = 0; i < 8; i++) {
        int u = i*256 + t;
        int hl = u >> 10, rem = u & 1023;
        int row = rem >> 3, grp = rem & 7;
        const __nv_bfloat16* src = (hl ? Al : Ah) + (int64_t)(mbase + row)*ldA + k0 + grp*8;
        cpa16(smb + (uint32_t)(((buf*2 + hl)*128 + row)*72 + grp*8)*2u, src);
    }
#pragma unroll
    for (int i = 0; i < 2; i++) {
        int u = i*256 + t;
        int hl = u >> 8, rem = u & 255;
        int row = rem >> 3, grp = rem & 7;
        const __nv_bfloat16* src = (hl ? Wl : Wh) + (int64_t)(nbase + row)*ldW + k0 + grp*8;
        cpa16(smb + (uint32_t)(36864 + ((buf*2 + hl)*32 + row)*72 + grp*8)*2u, src);
    }
    CP_COMMIT;
}

template<int OUT, int ACT>
__global__ __launch_bounds__(256) void mma_gemm(
    const __nv_bfloat16* __restrict__ Ah, const __nv_bfloat16* __restrict__ Al, int ldA,
    const __nv_bfloat16* __restrict__ Wh, const __nv_bfloat16* __restrict__ Wl, int ldW,
    int N, int KT, const float* __restrict__ bias,
    float* __restrict__ Cf, __nv_bfloat16* __restrict__ Ch, __nv_bfloat16* __restrict__ Cl, int ldC) {
    extern __shared__ char smraw[];
    uint32_t smb = (uint32_t)__cvta_generic_to_shared(smraw);
    const int t = threadIdx.x, lane = t & 31, w = t >> 5;
    const int wm = w & 3, wn = w >> 2;
    const int mbase = blockIdx.y*128, nbase = blockIdx.x*32;

    float acc[2][2][4];
#pragma unroll
    for (int a = 0; a < 2; a++)
#pragma unroll
        for (int b2 = 0; b2 < 2; b2++)
#pragma unroll
            for (int r = 0; r < 4; r++) acc[a][b2][r] = 0.f;

    load_chunk_g(smb, 0, t, 0, Ah, Al, ldA, mbase, Wh, Wl, ldW, nbase);

    for (int kc = 0; kc < KT; kc++) {
        const int cur = kc & 1;
        if (kc + 1 < KT) {
            load_chunk_g(smb, cur ^ 1, t, (kc+1)*64, Ah, Al, ldA, mbase, Wh, Wl, ldW, nbase);
            CP_WAIT1;
        } else { CP_WAIT0; }
        __syncthreads();
#pragma unroll
        for (int kk16 = 0; kk16 < 64; kk16 += 16) {
            uint32_t bh[2][2], bl[2][2];
#pragma unroll
            for (int nf = 0; nf < 2; nf++) {
                int rowW = wn*16 + nf*8 + (lane & 7);
                int kcol = kk16 + ((lane >> 3) & 1)*8;
                ldmx2(smb + (uint32_t)(36864 + ((cur*2+0)*32 + rowW)*72 + kcol)*2u, bh[nf]);
                ldmx2(smb + (uint32_t)(36864 + ((cur*2+1)*32 + rowW)*72 + kcol)*2u, bl[nf]);
            }
#pragma unroll
            for (int mf = 0; mf < 2; mf++) {
                int rowA = wm*32 + mf*16 + (lane & 7) + ((lane >> 3) & 1)*8;
                int kcol = kk16 + ((lane >> 4) & 1)*8;
                uint32_t ah[4], al[4];
                ldmx4(smb + (uint32_t)(((cur*2+0)*128 + rowA)*72 + kcol)*2u, ah);
                ldmx4(smb + (uint32_t)(((cur*2+1)*128 + rowA)*72 + kcol)*2u, al);
#pragma unroll
                for (int nf = 0; nf < 2; nf++) {
                    mma16816(acc[mf][nf], ah, bh[nf]);
                    mma16816(acc[mf][nf], al, bh[nf]);
                    mma16816(acc[mf][nf], ah, bl[nf]);
                }
            }
        }
        __syncthreads();
    }

    const int g2 = lane >> 2, q2 = (lane & 3)*2;
#pragma unroll
    for (int mf = 0; mf < 2; mf++)
#pragma unroll
        for (int nf = 0; nf < 2; nf++)
#pragma unroll
            for (int r = 0; r < 4; r++) {
                int row = mbase + wm*32 + mf*16 + g2 + (r >> 1)*8;
                int col = nbase + wn*16 + nf*8 + q2 + (r & 1);
                if (col < N) {
                    float v = acc[mf][nf][r];
                    if (bias) v += bias[col];
                    if (ACT == 1) v = fmaxf(v, 0.f);
                    if (ACT == 2) v = tanhf(v);
                    if (OUT == 0) Cf[(int64_t)row*ldC + col] = v;
                    else if (OUT == 1) {
                        __nv_bfloat16 hv = __float2bfloat16(v);
                        Ch[(int64_t)row*ldC + col] = hv;
                        Cl[(int64_t)row*ldC + col] = __float2bfloat16(v - __bfloat162float(hv));
                    } else {
                        size_t tix = ((size_t)(col >> 6)*128 + row)*72 + (col & 63);
                        __nv_bfloat16 hv = __float2bfloat16(v);
                        Ch[tix] = hv;
                        Cl[tix] = __float2bfloat16(v - __bfloat162float(hv));
                    }
                }
            }
}

// ---- launcher ----
#define GSA(p, s) cudaGetSymbolAddress((void**)&p, s)

extern "C" void kernel_launch(void* const* d_in, const int* in_sizes, int n_in,
                              void* d_out, int out_size) {
    const int* src_seqs = (const int*)d_in[0];
    const int* src_len = (const int*)d_in[1];
    const int* trg_nt = (const int*)d_in[2];
    const int* par_nt = (const int*)d_in[3];
    const int* par_lex = (const int*)d_in[4];
    const float* lex_emb = (const float*)d_in[5];
    const float* nt_emb = (const float*)d_in[6];
    const float* enc_Wih = (const float*)d_in[7];
    const float* enc_Whh = (const float*)d_in[8];
    const float* enc_b = (const float*)d_in[9];
    const float* dec_Wih = (const float*)d_in[10];
    const float* dec_Whh = (const float*)d_in[11];
    const float* dec_b = (const float*)d_in[12];
    const float* Wh1 = (const float*)d_in[13];
    const float* bh1 = (const float*)d_in[14];
    const float* Wh2 = (const float*)d_in[15];
    const float* bh2 = (const float*)d_in[16];
    const float* Wc1 = (const float*)d_in[17];
    const float* bc1 = (const float*)d_in[18];
    const float* Wc2 = (const float*)d_in[19];
    const float* bc2 = (const float*)d_in[20];
    const float* Wa = (const float*)d_in[21];
    const float* ba = (const float*)d_in[22];
    const float* Wqk = (const float*)d_in[23];
    const float* bqk = (const float*)d_in[24];
    const float* Wqv = (const float*)d_in[25];
    const float* bqv = (const float*)d_in[26];
    float* out = (float*)d_out;

    cudaFuncSetAttribute(mma_gemm<0,0>, cudaFuncAttributeMaxDynamicSharedMemorySize, GEN_SMEM);
    cudaFuncSetAttribute(mma_gemm<0,2>, cudaFuncAttributeMaxDynamicSharedMemorySize, GEN_SMEM);
    cudaFuncSetAttribute(mma_gemm<1,0>, cudaFuncAttributeMaxDynamicSharedMemorySize, GEN_SMEM);
    cudaFuncSetAttribute(mma_gemm<1,1>, cudaFuncAttributeMaxDynamicSharedMemorySize, GEN_SMEM);
    cudaFuncSetAttribute(mma_gemm<2,0>, cudaFuncAttributeMaxDynamicSharedMemorySize, GEN_SMEM);
    cudaFuncSetAttribute(enc_persist, cudaFuncAttributeMaxDynamicSharedMemorySize, ENC_SMEM);
    cudaFuncSetAttribute(dec_persist, cudaFuncAttributeMaxDynamicSharedMemorySize, DEC_SMEM);

    __nv_bfloat16 *WerHc,*WerLc,*WdrHc,*WdrLc,*WaHc,*WaLc;
    __nv_bfloat16 *WeiH,*WeiL,*WdiH,*WdiL,*WqkH,*WqkL,*WqvH,*WqvL;
    __nv_bfloat16 *Wh1H,*Wh1L,*Wh2H,*Wh2L,*Wc1H,*Wc1L,*Wc2H,*Wc2L;
    __nv_bfloat16 *seH,*seL,*aeH,*aeL,*shH,*shL,*ehH,*ehL,*ecH,*ecL,*t1H,*t1L,*dAT;
    float *encpre,*decpre,*qkey,*qval,*ec,*dc;
    GSA(WerHc,g_WerHc); GSA(WerLc,g_WerLc); GSA(WdrHc,g_WdrHc); GSA(WdrLc,g_WdrLc);
    GSA(WaHc,g_WaHc); GSA(WaLc,g_WaLc);
    GSA(WeiH,g_WeiH); GSA(WeiL,g_WeiL); GSA(WdiH,g_WdiH); GSA(WdiL,g_WdiL);
    GSA(WqkH,g_WqkH); GSA(WqkL,g_WqkL); GSA(WqvH,g_WqvH); GSA(WqvL,g_WqvL);
    GSA(Wh1H,g_Wh1H); GSA(Wh1L,g_Wh1L); GSA(Wh2H,g_Wh2H); GSA(Wh2L,g_Wh2L);
    GSA(Wc1H,g_Wc1H); GSA(Wc1L,g_Wc1L); GSA(Wc2H,g_Wc2H); GSA(Wc2L,g_Wc2L);
    GSA(seH,g_seH); GSA(seL,g_seL); GSA(aeH,g_aeH); GSA(aeL,g_aeL);
    GSA(shH,g_shH); GSA(shL,g_shL); GSA(ehH,g_ehH); GSA(ehL,g_ehL);
    GSA(ecH,g_ecH); GSA(ecL,g_ecL); GSA(t1H,g_t1H); GSA(t1L,g_t1L);
    GSA(dAT,g_dAT);
    GSA(encpre,g_encpre); GSA(decpre,g_decpre);
    GSA(qkey,g_qkey); GSA(qval,g_qval); GSA(ec,g_ec); GSA(dc,g_dc);

    // setup
    convwc_kernel<<<1024,256>>>(WerHc, WerLc, enc_Whh, nullptr, ECH, 128, 32, 1024, 1);
    convwc_kernel<<<1024,256>>>(WdrHc, WdrLc, dec_Whh, dec_Wih, DCH, 128, 32, 1324, 2);
    convwc_kernel<<<128,256>>>(WaHc, WaLc, Wa, nullptr, 16, 14, 8, 1024, 3);
    convw_kernel<<<1024,256>>>(WeiH, WeiL, enc_Wih, 4096, 0, KSE, 300, 300, 1);
    convw_kernel<<<1024,256>>>(WdiH, WdiL, dec_Wih, 4096, 0, KAE, 556, 856, 1);
    convw_kernel<<<256,256>>>(WqkH, WqkL, Wqk, 128, 100, 1024, 1024, 1024, 0);
    convw_kernel<<<256,256>>>(WqvH, WqvL, Wqv, 320, 300, 1024, 1024, 1024, 0);
    convw_kernel<<<1024,256>>>(Wh1H, Wh1L, Wh1, 2048, 2048, 1024, 1024, 1024, 0);
    convw_kernel<<<1024,256>>>(Wh2H, Wh2L, Wh2, 1024, 1024, 2048, 2048, 2048, 0);
    convw_kernel<<<1024,256>>>(Wc1H, Wc1L, Wc1, 2048, 2048, 1024, 1024, 1024, 0);
    convw_kernel<<<1024,256>>>(Wc2H, Wc2L, Wc2, 1024, 1024, 2048, 2048, 2048, 0);
    gather_kernel<<<2048,256>>>(src_seqs, trg_nt, par_nt, par_lex, lex_emb, nt_emb);

    // input-side precompute
    mma_gemm<0,0><<<dim3(128,128), 256, GEN_SMEM>>>(seH, seL, KSE, WeiH, WeiL, KSE,
        4096, KSE/64, nullptr, encpre, nullptr, nullptr, 4096);
    mma_gemm<0,0><<<dim3(128,64), 256, GEN_SMEM>>>(aeH, aeL, KAE, WdiH, WdiL, KAE,
        4096, KAE/64, nullptr, decpre, nullptr, nullptr, 4096);

    // encoder (persistent, bulk-copy pipelined)
    enc_persist<<<128, 256, ENC_SMEM>>>(enc_b, src_len);

    // attention keys/values
    mma_gemm<0,2><<<dim3(4,128), 256, GEN_SMEM>>>(shH, shL, H, WqkH, WqkL, 1024,
        100, 16, bqk, qkey, nullptr, nullptr, 112);
    mma_gemm<0,0><<<dim3(10,128), 256, GEN_SMEM>>>(shH, shL, H, WqvH, WqvL, 1024,
        300, 16, bqv, qval, nullptr, nullptr, 304);

    // decoder init MLPs (dh0 written chunked into g_dAT[0])
    convw_kernel<<<256,256>>>(ecH, ecL, ec, 128, 128, 1024, 1024, 1024, 0);
    mma_gemm<1,1><<<dim3(64,1), 256, GEN_SMEM>>>(ehH, ehL, H, Wh1H, Wh1L, 1024,
        2048, 16, bh1, nullptr, t1H, t1L, 2048);
    mma_gemm<2,0><<<dim3(32,1), 256, GEN_SMEM>>>(t1H, t1L, 2048, Wh2H, Wh2L, 2048,
        1024, 32, bh2, nullptr, dAT, dAT + (size_t)DCH*ACH, 0);
    mma_gemm<1,1><<<dim3(64,1), 256, GEN_SMEM>>>(ecH, ecL, H, Wc1H, Wc1L, 1024,
        2048, 16, bc1, nullptr, t1H, t1L, 2048);
    mma_gemm<0,0><<<dim3(32,1), 256, GEN_SMEM>>>(t1H, t1L, 2048, Wc2H, Wc2L, 2048,
        1024, 32, bc2, dc, nullptr, nullptr, 1024);

    // decoder (persistent, attention fused, bulk-copy pipelined)
    dec_persist<<<128, 256, DEC_SMEM>>>(dec_b, ba, src_len, out);
}

// round 9
// speedup vs baseline: 1.0451x; 1.0451x over previous
#include <cuda_runtime.h>
#include <cuda_bf16.h>
#include <math.h>
#include <stdint.h>

#define B 128
#define S_SRC 128
#define S_TRG 64
#define H 1024
#define KE 1024
#define KDR 1344
#define KSE 320
#define KAE 576
#define ECH 16
#define DCH 21
#define STGB (288*72*2)
#define ENC_SMEM ((ECH*32*72 + 3*288*72)*2)
#define DEC_SMEM ((DCH*32*72 + 3*288*72)*2)
#define GEN_SMEM 92160

// ---------------- weights (bf16 hi/lo, converted once) ----------------
__device__ __nv_bfloat16 g_WerH[4096*KE],  g_WerL[4096*KE];
__device__ __nv_bfloat16 g_WdrH[4096*KDR], g_WdrL[4096*KDR];
__device__ __nv_bfloat16 g_WeiH[4096*KSE], g_WeiL[4096*KSE];
__device__ __nv_bfloat16 g_WdiH[4096*KAE], g_WdiL[4096*KAE];
__device__ __nv_bfloat16 g_WqkH[128*1024], g_WqkL[128*1024];
__device__ __nv_bfloat16 g_WqvH[320*1024], g_WqvL[320*1024];
__device__ __nv_bfloat16 g_WaH[128*1024],  g_WaL[128*1024];
__device__ __nv_bfloat16 g_Wh1H[2048*1024], g_Wh1L[2048*1024];
__device__ __nv_bfloat16 g_Wh2H[1024*2048], g_Wh2L[1024*2048];
__device__ __nv_bfloat16 g_Wc1H[2048*1024], g_Wc1L[2048*1024];
__device__ __nv_bfloat16 g_Wc2H[1024*2048], g_Wc2L[1024*2048];

// ---------------- activations / state ----------------
__device__ __nv_bfloat16 g_seH[(size_t)S_SRC*B*KSE], g_seL[(size_t)S_SRC*B*KSE];
__device__ __nv_bfloat16 g_aeH[(size_t)S_TRG*B*KAE], g_aeL[(size_t)S_TRG*B*KAE];
__device__ float g_encpre[(size_t)S_SRC*B*4096];
__device__ float g_decpre[(size_t)S_TRG*B*4096];
__device__ __nv_bfloat16 g_shH[(size_t)B*S_SRC*H], g_shL[(size_t)B*S_SRC*H];
__device__ float g_qkey[(size_t)B*S_SRC*112];
__device__ float g_qval[(size_t)B*S_SRC*304];
__device__ __nv_bfloat16 g_ehH[2*B*H], g_ehL[2*B*H];
__device__ __nv_bfloat16 g_dAH[2*B*KDR], g_dAL[2*B*KDR];
__device__ float g_ec[B*H], g_dc[B*H];
__device__ __nv_bfloat16 g_ecH[B*H], g_ecL[B*H];
__device__ __nv_bfloat16 g_t1H[B*2048], g_t1L[B*2048];
__device__ float g_akey[B*112];
__device__ unsigned g_bar1, g_bar2;

#define CP_COMMIT asm volatile("cp.async.commit_group;" ::: "memory")
#define CP_WAIT0  asm volatile("cp.async.wait_group 0;" ::: "memory")
#define CP_WAIT1  asm volatile("cp.async.wait_group 1;" ::: "memory")

__device__ __forceinline__ void ldmx4(uint32_t a, uint32_t* r) {
    asm volatile("ldmatrix.sync.aligned.m8n8.x4.shared.b16 {%0,%1,%2,%3}, [%4];"
                 : "=r"(r[0]),"=r"(r[1]),"=r"(r[2]),"=r"(r[3]) : "r"(a));
}
__device__ __forceinline__ void ldmx2(uint32_t a, uint32_t* r) {
    asm volatile("ldmatrix.sync.aligned.m8n8.x2.shared.b16 {%0,%1}, [%2];"
                 : "=r"(r[0]),"=r"(r[1]) : "r"(a));
}
__device__ __forceinline__ void mma16816(float* c, const uint32_t* a, const uint32_t* b) {
    asm volatile("mma.sync.aligned.m16n8k16.row.col.f32.bf16.bf16.f32 "
                 "{%0,%1,%2,%3},{%4,%5,%6,%7},{%8,%9},{%0,%1,%2,%3};"
                 : "+f"(c[0]),"+f"(c[1]),"+f"(c[2]),"+f"(c[3])
                 : "r"(a[0]),"r"(a[1]),"r"(a[2]),"r"(a[3]),"r"(b[0]),"r"(b[1]));
}
__device__ __forceinline__ void cpa16(uint32_t d, const void* s) {
    asm volatile("cp.async.cg.shared.global [%0], [%1], 16;" :: "r"(d),"l"(s));
}
__device__ __forceinline__ void grid_sync(unsigned* bar, unsigned target) {
    __syncthreads();
    if (threadIdx.x == 0) {
        __threadfence();
        atomicAdd(bar, 1u);
        volatile unsigned* vb = (volatile unsigned*)bar;
        while (*vb < target) __nanosleep(64);
        __threadfence();
    }
    __syncthreads();
}

// ---------------- setup kernels ----------------
__global__ void convw_kernel(__nv_bfloat16* dh, __nv_bfloat16* dl,
                             const float* __restrict__ s1, const float* __restrict__ s2,
                             int Npad, int Nreal, int Kpad, int Kreal, int lds, int mode) {
    int64_t tot = (int64_t)Npad * Kpad;
    int64_t stride = (int64_t)gridDim.x * blockDim.x;
    for (int64_t i = (int64_t)blockIdx.x*blockDim.x + threadIdx.x; i < tot; i += stride) {
        int n = (int)(i / Kpad), k = (int)(i % Kpad);
        float v = 0.f;
        if (mode == 0) { if (n < Nreal && k < Kreal) v = s1[(int64_t)n*lds + k]; }
        else {
            int orig = (n & 3)*1024 + (n >> 2);
            if (mode == 1) { if (k < Kreal) v = s1[(int64_t)orig*lds + k]; }
            else {
                if (k < 1024) v = s1[(int64_t)orig*1024 + k];
                else if (k < 1324) v = s2[(int64_t)orig*856 + 556 + (k-1024)];
            }
        }
        __nv_bfloat16 hv = __float2bfloat16(v);
        dh[i] = hv;
        dl[i] = __float2bfloat16(v - __bfloat162float(hv));
    }
}

__global__ void gather_kernel(const int* __restrict__ src_seqs, const int* __restrict__ trg_nt,
                              const int* __restrict__ par_nt, const int* __restrict__ par_lex,
                              const float* __restrict__ lex_emb, const float* __restrict__ nt_emb) {
    if (blockIdx.x == 0 && threadIdx.x == 0) { g_bar1 = 0u; g_bar2 = 0u; }
    const int64_t nse = (int64_t)S_SRC*B*KSE;
    const int64_t nae = (int64_t)S_TRG*B*KAE;
    int64_t stride = (int64_t)gridDim.x * blockDim.x;
    for (int64_t i = (int64_t)blockIdx.x*blockDim.x + threadIdx.x; i < nse; i += stride) {
        {
            int d = (int)(i % KSE), r = (int)(i / KSE);
            int s = r >> 7, b = r & 127;
            float v = (d < 300) ? lex_emb[(int64_t)src_seqs[b*S_SRC+s]*300 + d] : 0.f;
            __nv_bfloat16 hv = __float2bfloat16(v);
            g_seH[i] = hv; g_seL[i] = __float2bfloat16(v - __bfloat162float(hv));
        }
        if (i < nae) {
            int d = (int)(i % KAE), r = (int)(i / KAE);
            int t = r >> 7, b = r & 127;
            float v = 0.f;
            if (d < 128)      v = nt_emb[(int64_t)trg_nt[b*S_TRG+t]*128 + d];
            else if (d < 256) v = nt_emb[(int64_t)par_nt[b*S_TRG+t]*128 + (d-128)];
            else if (d < 556) v = lex_emb[(int64_t)par_lex[b*S_TRG+t]*300 + (d-256)];
            __nv_bfloat16 hv = __float2bfloat16(v);
            g_aeH[i] = hv; g_aeL[i] = __float2bfloat16(v - __bfloat162float(hv));
        }
        if (i < 2*B*KDR) { g_dAH[i] = __float2bfloat16(0.f); g_dAL[i] = __float2bfloat16(0.f); }
        if (i < 2*B*H)   { g_ehH[i] = __float2bfloat16(0.f); g_ehL[i] = __float2bfloat16(0.f); }
        if (i < B*H)     g_ec[i] = 0.f;
    }
}

// ============ persistent recurrence machinery ============
__device__ __forceinline__ void stream_chunk(uint32_t st, int t, int k0,
    const __nv_bfloat16* __restrict__ Ah, const __nv_bfloat16* __restrict__ Al, int ldA,
    const __nv_bfloat16* __restrict__ Wl, int ldW, int nbase)
{
#pragma unroll
    for (int i = 0; i < 9; i++) {
        int u = i*256 + t;
        int row = u >> 3, grp = u & 7;
        const __nv_bfloat16* src;
        if (row < 128)      src = Ah + (int64_t)row*ldA + k0 + grp*8;
        else if (row < 256) src = Al + (int64_t)(row-128)*ldA + k0 + grp*8;
        else                src = Wl + (int64_t)(nbase + row - 256)*ldW + k0 + grp*8;
        cpa16(st + (uint32_t)(row*72 + grp*8)*2u, src);
    }
    CP_COMMIT;
}

template<int KCH>
__device__ __forceinline__ void load_resident(uint32_t smW, int t,
    const __nv_bfloat16* __restrict__ Whg, int ldW, int nbase)
{
    int rr = (t >> 3) & 31, grp = t & 7;
#pragma unroll
    for (int i = 0; i < KCH; i++)
        cpa16(smW + (uint32_t)((i*32 + rr)*72 + grp*8)*2u,
              Whg + (int64_t)(nbase + rr)*ldW + i*64 + grp*8);
    CP_COMMIT; CP_WAIT0;
    __syncthreads();
}

__device__ __forceinline__ void mma_chunk(uint32_t smWc, uint32_t st,
    int lane, int wm, int wn, float acc[2][2][4])
{
#pragma unroll
    for (int kk16 = 0; kk16 < 64; kk16 += 16) {
        uint32_t bh[2][2], bl[2][2];
#pragma unroll
        for (int nf = 0; nf < 2; nf++) {
            int rowW = wn*16 + nf*8 + (lane & 7);
            int kcol = kk16 + ((lane >> 3) & 1)*8;
            ldmx2(smWc + (uint32_t)(rowW*72 + kcol)*2u, bh[nf]);
            ldmx2(st + (uint32_t)((256 + rowW)*72 + kcol)*2u, bl[nf]);
        }
#pragma unroll
        for (int mf = 0; mf < 2; mf++) {
            int rowA = wm*32 + mf*16 + (lane & 7) + ((lane >> 3) & 1)*8;
            int kcol = kk16 + ((lane >> 4) & 1)*8;
            uint32_t ah[4], al[4];
            ldmx4(st + (uint32_t)(rowA*72 + kcol)*2u, ah);
            ldmx4(st + (uint32_t)((128 + rowA)*72 + kcol)*2u, al);
#pragma unroll
            for (int nf = 0; nf < 2; nf++) {
                mma16816(acc[mf][nf], ah, bh[nf]);
                mma16816(acc[mf][nf], al, bh[nf]);
                mma16816(acc[mf][nf], ah, bl[nf]);
            }
        }
    }
}

template<int KCH>
__device__ __forceinline__ void gemm_phase(uint32_t smW, uint32_t smS, int t, int lane,
    int wm, int wn,
    const __nv_bfloat16* __restrict__ Ah, const __nv_bfloat16* __restrict__ Al, int ldA,
    const __nv_bfloat16* __restrict__ Wlg, int ldW, int nbase, float acc[2][2][4])
{
    stream_chunk(smS, t, 0, Ah, Al, ldA, Wlg, ldW, nbase);
    stream_chunk(smS + STGB, t, 64, Ah, Al, ldA, Wlg, ldW, nbase);
    for (int c = 0; c < KCH; c++) {
        if (c < KCH - 1) { CP_WAIT1; } else { CP_WAIT0; }
        __syncthreads();
        if (c + 2 < KCH)
            stream_chunk(smS + ((c+2)%3)*STGB, t, (c+2)*64, Ah, Al, ldA, Wlg, ldW, nbase);
        mma_chunk(smW + (uint32_t)c*(32*72*2), smS + (c%3)*STGB, lane, wm, wn, acc);
    }
    __syncthreads();
}

// ---------------- persistent encoder ----------------
__global__ __launch_bounds__(256) void enc_persist(const float* __restrict__ biasv,
                                                   const int* __restrict__ lens) {
    extern __shared__ char smraw[];
    const uint32_t smb = (uint32_t)__cvta_generic_to_shared(smraw);
    const uint32_t smW = smb;
    const uint32_t smS = smb + (uint32_t)(ECH*32*72*2);
    const int t = threadIdx.x;
    const int lane = t & 31, w = t >> 5;
    const int wm = w & 3, wn = w >> 2;
    const int nbase = blockIdx.x*32;
    const int g2 = lane >> 2, q2 = (lane & 3)*2;

    load_resident<ECH>(smW, t, g_WerH, KE, nbase);

    unsigned target = 0;
    for (int s = 0; s < S_SRC; s++) {
        const int p = s & 1;
        const __nv_bfloat16* Ah = g_ehH + p*B*H;
        const __nv_bfloat16* Al = g_ehL + p*B*H;
        __nv_bfloat16* HoH = g_ehH + (p^1)*B*H;
        __nv_bfloat16* HoL = g_ehL + (p^1)*B*H;
        const float* add = g_encpre + (int64_t)s*B*4096;

        float acc[2][2][4];
#pragma unroll
        for (int a = 0; a < 2; a++)
#pragma unroll
            for (int b2 = 0; b2 < 2; b2++)
#pragma unroll
                for (int r = 0; r < 4; r++) acc[a][b2][r] = 0.f;

        gemm_phase<ECH>(smW, smS, t, lane, wm, wn, Ah, Al, H, g_WerL, KE, nbase, acc);

        float* zb = (float*)(smraw + ECH*32*72*2);
#pragma unroll
        for (int mf = 0; mf < 2; mf++)
#pragma unroll
            for (int nf = 0; nf < 2; nf++)
#pragma unroll
                for (int r = 0; r < 4; r++) {
                    int row = wm*32 + mf*16 + g2 + (r >> 1)*8;
                    int col = wn*16 + nf*8 + q2 + (r & 1);
                    zb[row*33 + col] = acc[mf][nf][r];
                }
        __syncthreads();

        const int b = t & 127;
        const int jj0 = (t >> 7)*4;
        bool valid = s < lens[b];
        __nv_bfloat16 z16 = __float2bfloat16(0.f);
#pragma unroll
        for (int jj = jj0; jj < jj0 + 4; jj++) {
            int jglob = (nbase >> 2) + jj;
            float4 pre = *(const float4*)&add[(int64_t)b*4096 + nbase + jj*4];
            float zi = zb[b*33 + jj*4 + 0] + pre.x + biasv[jglob];
            float zf = zb[b*33 + jj*4 + 1] + pre.y + biasv[1024 + jglob];
            float zg = zb[b*33 + jj*4 + 2] + pre.z + biasv[2048 + jglob];
            float zo = zb[b*33 + jj*4 + 3] + pre.w + biasv[3072 + jglob];
            float cold = g_ec[b*H + jglob];
            float si = 1.f/(1.f + expf(-zi));
            float sf = 1.f/(1.f + expf(-zf));
            float so = 1.f/(1.f + expf(-zo));
            float c2 = sf*cold + si*tanhf(zg);
            float h2 = so*tanhf(c2);
            if (valid) g_ec[b*H + jglob] = c2;
            __nv_bfloat16 nh = __float2bfloat16(h2);
            __nv_bfloat16 nl = __float2bfloat16(h2 - __bfloat162float(nh));
            HoH[b*H + jglob] = valid ? nh : Ah[b*H + jglob];
            HoL[b*H + jglob] = valid ? nl : Al[b*H + jglob];
            g_shH[((int64_t)b*S_SRC + s)*H + jglob] = valid ? nh : z16;
            g_shL[((int64_t)b*S_SRC + s)*H + jglob] = valid ? nl : z16;
        }
        grid_sync(&g_bar1, target += 128);
    }
}

// ---------------- persistent decoder ----------------
__device__ __forceinline__ void stream_mini(uint32_t st, int t, int k0,
    const __nv_bfloat16* __restrict__ Ah, const __nv_bfloat16* __restrict__ Al, int nb8)
{
#pragma unroll
    for (int i = 0; i < 9; i++) {
        int u = i*256 + t;
        if (u >= 2176) break;
        int row = u >> 3, grp = u & 7;
        const __nv_bfloat16* src;
        if (row < 128)      src = Ah + (int64_t)row*KDR + k0 + grp*8;
        else if (row < 256) src = Al + (int64_t)(row-128)*KDR + k0 + grp*8;
        else if (row < 264) src = g_WaH + (int64_t)(nb8 + row - 256)*1024 + k0 + grp*8;
        else                src = g_WaL + (int64_t)(nb8 + row - 264)*1024 + k0 + grp*8;
        cpa16(st + (uint32_t)(row*72 + grp*8)*2u, src);
    }
    CP_COMMIT;
}

__global__ __launch_bounds__(256) void dec_persist(const float* __restrict__ biasv,
                                                   const float* __restrict__ ba_,
                                                   const int* __restrict__ lens,
                                                   float* __restrict__ outF) {
    extern __shared__ char smraw[];
    __shared__ float s_ak[112];
    __shared__ float s_en[128];
    __shared__ float s_red[8];
    const uint32_t smb = (uint32_t)__cvta_generic_to_shared(smraw);
    const uint32_t smW = smb;
    const uint32_t smS = smb + (uint32_t)(DCH*32*72*2);
    const int t = threadIdx.x;
    const int lane = t & 31, w = t >> 5;
    const int wm = w & 3, wn = w >> 2;
    const int nbase = blockIdx.x*32;
    const int g2 = lane >> 2, q2 = (lane & 3)*2;
    const int myb = blockIdx.x;

    load_resident<DCH>(smW, t, g_WdrH, KDR, nbase);

    unsigned target = 0;
    for (int ts = 0; ts < S_TRG; ts++) {
        const int p = ts & 1;
        __nv_bfloat16* dAh = g_dAH + p*B*KDR;
        __nv_bfloat16* dAl = g_dAL + p*B*KDR;
        __nv_bfloat16* nAh = g_dAH + (p^1)*B*KDR;
        __nv_bfloat16* nAl = g_dAL + (p^1)*B*KDR;

        if (blockIdx.x < 14) {
            const int nb8 = blockIdx.x*8;
            float acm[4] = {0.f,0.f,0.f,0.f};
            stream_mini(smS, t, 0, dAh, dAl, nb8);
            for (int c = 0; c < 16; c++) {
                if (c < 15) stream_mini(smS + ((c+1)&1)*STGB, t, (c+1)*64, dAh, dAl, nb8);
                if (c < 15) { CP_WAIT1; } else { CP_WAIT0; }
                __syncthreads();
                uint32_t st = smS + (c & 1)*STGB;
#pragma unroll
                for (int kk16 = 0; kk16 < 64; kk16 += 16) {
                    uint32_t bh[2], bl[2];
                    int rowW = lane & 7;
                    int kcolW = kk16 + ((lane >> 3) & 1)*8;
                    ldmx2(st + (uint32_t)((256 + rowW)*72 + kcolW)*2u, bh);
                    ldmx2(st + (uint32_t)((264 + rowW)*72 + kcolW)*2u, bl);
                    int rowA = w*16 + (lane & 7) + ((lane >> 3) & 1)*8;
                    int kcolA = kk16 + ((lane >> 4) & 1)*8;
                    uint32_t ah[4], al[4];
                    ldmx4(st + (uint32_t)(rowA*72 + kcolA)*2u, ah);
                    ldmx4(st + (uint32_t)((128 + rowA)*72 + kcolA)*2u, al);
                    mma16816(acm, ah, bh);
                    mma16816(acm, al, bh);
                    mma16816(acm, ah, bl);
                }
                __syncthreads();
            }
#pragma unroll
            for (int r = 0; r < 4; r++) {
                int row = w*16 + g2 + (r >> 1)*8;
                int gc = nb8 + q2 + (r & 1);
                float bb = (gc < 100) ? ba_[gc] : 0.f;
                g_akey[row*112 + gc] = tanhf(acm[r] + bb);
            }
        }
        grid_sync(&g_bar2, target += 128);

        {
            if (t < 112) s_ak[t] = g_akey[myb*112 + t];
            __syncthreads();
            float ex = 0.f;
            if (t < 128) {
                int L = lens[myb];
                const float* qk = g_qkey + ((int64_t)myb*S_SRC + t)*112;
                float pp = 0.f;
#pragma unroll 4
                for (int d = 0; d < 100; d++) pp = fmaf(qk[d], s_ak[d], pp);
                float e = (t < L) ? pp : -1e9f;
                float mx = e;
                for (int o = 16; o; o >>= 1) mx = fmaxf(mx, __shfl_xor_sync(0xffffffffu, mx, o));
                if (lane == 0) s_red[w] = mx;
                s_en[t] = e;
            }
            __syncthreads();
            if (t < 128) {
                float mx = fmaxf(fmaxf(s_red[0], s_red[1]), fmaxf(s_red[2], s_red[3]));
                ex = expf(s_en[t] - mx);
                float sm = ex;
                for (int o = 16; o; o >>= 1) sm += __shfl_xor_sync(0xffffffffu, sm, o);
                if (lane == 0) s_red[4 + w] = sm;
            }
            __syncthreads();
            if (t < 128) s_en[t] = ex;
            __syncthreads();
            float denom = s_red[4] + s_red[5] + s_red[6] + s_red[7];
            for (int d = t; d < 300; d += 256) {
                float c = 0.f;
#pragma unroll 4
                for (int s2 = 0; s2 < S_SRC; s2++)
                    c = fmaf(s_en[s2], g_qval[((int64_t)myb*S_SRC + s2)*304 + d], c);
                c /= denom;
                __nv_bfloat16 hv = __float2bfloat16(c);
                dAh[(int64_t)myb*KDR + 1024 + d] = hv;
                dAl[(int64_t)myb*KDR + 1024 + d] = __float2bfloat16(c - __bfloat162float(hv));
            }
        }
        grid_sync(&g_bar2, target += 128);

        {
            const float* add = g_decpre + (int64_t)ts*B*4096;
            float acc[2][2][4];
#pragma unroll
            for (int a = 0; a < 2; a++)
#pragma unroll
                for (int b2 = 0; b2 < 2; b2++)
#pragma unroll
                    for (int r = 0; r < 4; r++) acc[a][b2][r] = 0.f;

            gemm_phase<DCH>(smW, smS, t, lane, wm, wn, dAh, dAl, KDR, g_WdrL, KDR, nbase, acc);

            float* zb = (float*)(smraw + DCH*32*72*2);
#pragma unroll
            for (int mf = 0; mf < 2; mf++)
#pragma unroll
                for (int nf = 0; nf < 2; nf++)
#pragma unroll
                    for (int r = 0; r < 4; r++) {
                        int row = wm*32 + mf*16 + g2 + (r >> 1)*8;
                        int col = wn*16 + nf*8 + q2 + (r & 1);
                        zb[row*33 + col] = acc[mf][nf][r];
                    }
            __syncthreads();

            const int b = t & 127;
            const int jj0 = (t >> 7)*4;
#pragma unroll
            for (int jj = jj0; jj < jj0 + 4; jj++) {
                int jglob = (nbase >> 2) + jj;
                float4 pre = *(const float4*)&add[(int64_t)b*4096 + nbase + jj*4];
                float zi = zb[b*33 + jj*4 + 0] + pre.x + biasv[jglob];
                float zf = zb[b*33 + jj*4 + 1] + pre.y + biasv[1024 + jglob];
                float zg = zb[b*33 + jj*4 + 2] + pre.z + biasv[2048 + jglob];
                float zo = zb[b*33 + jj*4 + 3] + pre.w + biasv[3072 + jglob];
                float cold = g_dc[b*H + jglob];
                float si = 1.f/(1.f + expf(-zi));
                float sf = 1.f/(1.f + expf(-zf));
                float so = 1.f/(1.f + expf(-zo));
                float c2 = sf*cold + si*tanhf(zg);
                float h2 = so*tanhf(c2);
                g_dc[b*H + jglob] = c2;
                __nv_bfloat16 nh = __float2bfloat16(h2);
                __nv_bfloat16 nl = __float2bfloat16(h2 - __bfloat162float(nh));
                nAh[(int64_t)b*KDR + jglob] = nh;
                nAl[(int64_t)b*KDR + jglob] = nl;
                outF[((int64_t)b*S_TRG + ts)*H + jglob] = h2;
            }
        }
        grid_sync(&g_bar2, target += 128);
    }
}

// ---------------- one-shot GEMM ----------------
__device__ __forceinline__ void load_chunk_g(uint32_t smb, int buf, int t, int k0,
    const __nv_bfloat16* __restrict__ Ah, const __nv_bfloat16* __restrict__ Al, int ldA, int mbase,
    const __nv_bfloat16* __restrict__ Wh, const __nv_bfloat16* __restrict__ Wl, int ldW, int nbase)
{
#pragma unroll
    for (int i = 0; i < 8; i++) {
        int u = i*256 + t;
        int hl = u >> 10, rem = u & 1023;
        int row = rem >> 3, grp = rem & 7;
        const __nv_bfloat16* src = (hl ? Al : Ah) + (int64_t)(mbase + row)*ldA + k0 + grp*8;
        cpa16(smb + (uint32_t)(((buf*2 + hl)*128 + row)*72 + grp*8)*2u, src);
    }
#pragma unroll
    for (int i = 0; i < 2; i++) {
        int u = i*256 + t;
        int hl = u >> 8, rem = u & 255;
        int row = rem >> 3, grp = rem & 7;
        const __nv_bfloat16* src = (hl ? Wl : Wh) + (int64_t)(nbase + row)*ldW + k0 + grp*8;
        cpa16(smb + (uint32_t)(36864 + ((buf*2 + hl)*32 + row)*72 + grp*8)*2u, src);
    }
    CP_COMMIT;
}

template<int OUT, int ACT>   // OUT: 0 fp32, 1 bf16 hi/lo ; ACT: 0 none, 1 relu, 2 tanh
__global__ __launch_bounds__(256) void mma_gemm(
    const __nv_bfloat16* __restrict__ Ah, const __nv_bfloat16* __restrict__ Al, int ldA,
    const __nv_bfloat16* __restrict__ Wh, const __nv_bfloat16* __restrict__ Wl, int ldW,
    int N, int KT, const float* __restrict__ bias,
    float* __restrict__ Cf, __nv_bfloat16* __restrict__ Ch, __nv_bfloat16* __restrict__ Cl, int ldC)
{
    extern __shared__ char smraw[];
    uint32_t smb = (uint32_t)__cvta_generic_to_shared(smraw);
    const int t = threadIdx.x;
    const int lane = t & 31, w = t >> 5;
    const int wm = w & 3, wn = w >> 2;
    const int mbase = blockIdx.y*128;
    const int nbase = blockIdx.x*32;

    float acc[2][2][4];
#pragma unroll
    for (int a = 0; a < 2; a++)
#pragma unroll
        for (int b2 = 0; b2 < 2; b2++)
#pragma unroll
            for (int r = 0; r < 4; r++) acc[a][b2][r] = 0.f;

    load_chunk_g(smb, 0, t, 0, Ah, Al, ldA, mbase, Wh, Wl, ldW, nbase);

    for (int kc = 0; kc < KT; kc++) {
        const int cur = kc & 1;
        if (kc + 1 < KT) {
            load_chunk_g(smb, cur ^ 1, t, (kc+1)*64, Ah, Al, ldA, mbase, Wh, Wl, ldW, nbase);
            CP_WAIT1;
        } else { CP_WAIT0; }
        __syncthreads();
#pragma unroll
        for (int kk16 = 0; kk16 < 64; kk16 += 16) {
            uint32_t bh[2][2], bl[2][2];
#pragma unroll
            for (int nf = 0; nf < 2; nf++) {
                int rowW = wn*16 + nf*8 + (lane & 7);
                int kcol = kk16 + ((lane >> 3) & 1)*8;
                ldmx2(smb + (uint32_t)(36864 + ((cur*2+0)*32 + rowW)*72 + kcol)*2u, bh[nf]);
                ldmx2(smb + (uint32_t)(36864 + ((cur*2+1)*32 + rowW)*72 + kcol)*2u, bl[nf]);
            }
#pragma unroll
            for (int mf = 0; mf < 2; mf++) {
                int rowA = wm*32 + mf*16 + (lane & 7) + ((lane >> 3) & 1)*8;
                int kcol = kk16 + ((lane >> 4) & 1)*8;
                uint32_t ah[4], al[4];
                ldmx4(smb + (uint32_t)(((cur*2+0)*128 + rowA)*72 + kcol)*2u, ah);
                ldmx4(smb + (uint32_t)(((cur*2+1)*128 + rowA)*72 + kcol)*2u, al);
#pragma unroll
                for (int nf = 0; nf < 2; nf++) {
                    mma16816(acc[mf][nf], ah, bh[nf]);
                    mma16816(acc[mf][nf], al, bh[nf]);
                    mma16816(acc[mf][nf], ah, bl[nf]);
                }
            }
        }
        __syncthreads();
    }

    const int g2 = lane >> 2, q2 = (lane & 3)*2;
#pragma unroll
    for (int mf = 0; mf < 2; mf++)
#pragma unroll
        for (int nf = 0; nf < 2; nf++)
#pragma unroll
            for (int r = 0; r < 4; r++) {
                int row = mbase + wm*32 + mf*16 + g2 + (r >> 1)*8;
                int col = nbase + wn*16 + nf*8 + q2 + (r & 1);
                if (col < N) {
                    float v = acc[mf][nf][r];
                    if (bias) v += bias[col];
                    if (ACT == 1) v = fmaxf(v, 0.f);
                    if (ACT == 2) v = tanhf(v);
                    if (OUT == 0) Cf[(int64_t)row*ldC + col] = v;
                    else {
                        __nv_bfloat16 hv = __float2bfloat16(v);
                        Ch[(int64_t)row*ldC + col] = hv;
                        Cl[(int64_t)row*ldC + col] = __float2bfloat16(v - __bfloat162float(hv));
                    }
                }
            }
}

// ---------------- launcher (reordered so ncu -s 5 captures enc_persist) ----------------
#define GSA(p, s) cudaGetSymbolAddress((void**)&p, s)

extern "C" void kernel_launch(void* const* d_in, const int* in_sizes, int n_in,
                              void* d_out, int out_size) {
    const int* src_seqs = (const int*)d_in[0];
    const int* src_len = (const int*)d_in[1];
    const int* trg_nt = (const int*)d_in[2];
    const int* par_nt = (const int*)d_in[3];
    const int* par_lex = (const int*)d_in[4];
    const float* lex_emb = (const float*)d_in[5];
    const float* nt_emb = (const float*)d_in[6];
    const float* enc_Wih = (const float*)d_in[7];
    const float* enc_Whh = (const float*)d_in[8];
    const float* enc_b = (const float*)d_in[9];
    const float* dec_Wih = (const float*)d_in[10];
    const float* dec_Whh = (const float*)d_in[11];
    const float* dec_b = (const float*)d_in[12];
    const float* Wh1 = (const float*)d_in[13];
    const float* bh1 = (const float*)d_in[14];
    const float* Wh2 = (const float*)d_in[15];
    const float* bh2 = (const float*)d_in[16];
    const float* Wc1 = (const float*)d_in[17];
    const float* bc1 = (const float*)d_in[18];
    const float* Wc2 = (const float*)d_in[19];
    const float* bc2 = (const float*)d_in[20];
    const float* Wa = (const float*)d_in[21];
    const float* ba = (const float*)d_in[22];
    const float* Wqk = (const float*)d_in[23];
    const float* bqk = (const float*)d_in[24];
    const float* Wqv = (const float*)d_in[25];
    const float* bqv = (const float*)d_in[26];
    float* out = (float*)d_out;

    cudaFuncSetAttribute(mma_gemm<0,0>, cudaFuncAttributeMaxDynamicSharedMemorySize, GEN_SMEM);
    cudaFuncSetAttribute(mma_gemm<0,2>, cudaFuncAttributeMaxDynamicSharedMemorySize, GEN_SMEM);
    cudaFuncSetAttribute(mma_gemm<1,0>, cudaFuncAttributeMaxDynamicSharedMemorySize, GEN_SMEM);
    cudaFuncSetAttribute(mma_gemm<1,1>, cudaFuncAttributeMaxDynamicSharedMemorySize, GEN_SMEM);
    cudaFuncSetAttribute(enc_persist, cudaFuncAttributeMaxDynamicSharedMemorySize, ENC_SMEM);
    cudaFuncSetAttribute(dec_persist, cudaFuncAttributeMaxDynamicSharedMemorySize, DEC_SMEM);

    __nv_bfloat16 *WerH,*WerL,*WdrH,*WdrL,*WeiH,*WeiL,*WdiH,*WdiL;
    __nv_bfloat16 *WqkH,*WqkL,*WqvH,*WqvL,*WaH,*WaL;
    __nv_bfloat16 *Wh1H,*Wh1L,*Wh2H,*Wh2L,*Wc1H,*Wc1L,*Wc2H,*Wc2L;
    __nv_bfloat16 *seH,*seL,*aeH,*aeL,*shH,*shL,*ehH,*ehL,*dAH,*dAL,*ecH,*ecL,*t1H,*t1L;
    float *encpre,*decpre,*qkey,*qval,*ec,*dc;
    GSA(WerH,g_WerH); GSA(WerL,g_WerL); GSA(WdrH,g_WdrH); GSA(WdrL,g_WdrL);
    GSA(WeiH,g_WeiH); GSA(WeiL,g_WeiL); GSA(WdiH,g_WdiH); GSA(WdiL,g_WdiL);
    GSA(WqkH,g_WqkH); GSA(WqkL,g_WqkL); GSA(WqvH,g_WqvH); GSA(WqvL,g_WqvL);
    GSA(WaH,g_WaH);   GSA(WaL,g_WaL);
    GSA(Wh1H,g_Wh1H); GSA(Wh1L,g_Wh1L); GSA(Wh2H,g_Wh2H); GSA(Wh2L,g_Wh2L);
    GSA(Wc1H,g_Wc1H); GSA(Wc1L,g_Wc1L); GSA(Wc2H,g_Wc2H); GSA(Wc2L,g_Wc2L);
    GSA(seH,g_seH); GSA(seL,g_seL); GSA(aeH,g_aeH); GSA(aeL,g_aeL);
    GSA(shH,g_shH); GSA(shL,g_shL); GSA(ehH,g_ehH); GSA(ehL,g_ehL);
    GSA(dAH,g_dAH); GSA(dAL,g_dAL); GSA(ecH,g_ecH); GSA(ecL,g_ecL);
    GSA(t1H,g_t1H); GSA(t1L,g_t1L);
    GSA(encpre,g_encpre); GSA(decpre,g_decpre);
    GSA(qkey,g_qkey); GSA(qval,g_qval); GSA(ec,g_ec); GSA(dc,g_dc);

    // L0..L4: minimal deps for the encoder
    convw_kernel<<<1024, 256>>>(WerH, WerL, enc_Whh, nullptr, 4096, 0, KE, 1024, 1024, 1);   // L0
    convw_kernel<<<1024, 256>>>(WeiH, WeiL, enc_Wih, nullptr, 4096, 0, KSE, 300, 300, 1);    // L1
    gather_kernel<<<2048, 256>>>(src_seqs, trg_nt, par_nt, par_lex, lex_emb, nt_emb);        // L2
    mma_gemm<0,0><<<dim3(128,128), 256, GEN_SMEM>>>(seH, seL, KSE, WeiH, WeiL, KSE,
        4096, KSE/64, nullptr, encpre, nullptr, nullptr, 4096);                              // L3
    convw_kernel<<<1024, 256>>>(WdrH, WdrL, dec_Whh, dec_Wih, 4096, 0, KDR, 1324, 0, 2);     // L4

    // L5: encoder (persistent) — ncu -s 5 -c 1 captures THIS launch
    enc_persist<<<128, 256, ENC_SMEM>>>(enc_b, src_len);                                     // L5

    // remaining setup
    convw_kernel<<<1024, 256>>>(WdiH, WdiL, dec_Wih, nullptr, 4096, 0, KAE, 556, 856, 1);
    convw_kernel<<<256, 256>>>(WqkH, WqkL, Wqk, nullptr, 128, 100, 1024, 1024, 1024, 0);
    convw_kernel<<<256, 256>>>(WqvH, WqvL, Wqv, nullptr, 320, 300, 1024, 1024, 1024, 0);
    convw_kernel<<<256, 256>>>(WaH,  WaL,  Wa,  nullptr, 128, 100, 1024, 1024, 1024, 0);
    convw_kernel<<<1024, 256>>>(Wh1H, Wh1L, Wh1, nullptr, 2048, 2048, 1024, 1024, 1024, 0);
    convw_kernel<<<1024, 256>>>(Wh2H, Wh2L, Wh2, nullptr, 1024, 1024, 2048, 2048, 2048, 0);
    convw_kernel<<<1024, 256>>>(Wc1H, Wc1L, Wc1, nullptr, 2048, 2048, 1024, 1024, 1024, 0);
    convw_kernel<<<1024, 256>>>(Wc2H, Wc2L, Wc2, nullptr, 1024, 1024, 2048, 2048, 2048, 0);

    // dec input precompute
    mma_gemm<0,0><<<dim3(128,64), 256, GEN_SMEM>>>(aeH, aeL, KAE, WdiH, WdiL, KAE,
        4096, KAE/64, nullptr, decpre, nullptr, nullptr, 4096);

    // attention keys/values
    mma_gemm<0,2><<<dim3(4,128), 256, GEN_SMEM>>>(shH, shL, H, WqkH, WqkL, 1024,
        100, 16, bqk, qkey, nullptr, nullptr, 112);
    mma_gemm<0,0><<<dim3(10,128), 256, GEN_SMEM>>>(shH, shL, H, WqvH, WqvL, 1024,
        300, 16, bqv, qval, nullptr, nullptr, 304);

    // decoder init MLPs
    __nv_bfloat16* ehTH = ehH;
    __nv_bfloat16* ehTL = ehL;
    convw_kernel<<<256, 256>>>(ecH, ecL, ec, nullptr, 128, 128, 1024, 1024, 1024, 0);
    mma_gemm<1,1><<<dim3(64,1), 256, GEN_SMEM>>>(ehTH, ehTL, H, Wh1H, Wh1L, 1024,
        2048, 16, bh1, nullptr, t1H, t1L, 2048);
    mma_gemm<1,0><<<dim3(32,1), 256, GEN_SMEM>>>(t1H, t1L, 2048, Wh2H, Wh2L, 2048,
        1024, 32, bh2, nullptr, dAH, dAL, KDR);
    mma_gemm<1,1><<<dim3(64,1), 256, GEN_SMEM>>>(ecH, ecL, H, Wc1H, Wc1L, 1024,
        2048, 16, bc1, nullptr, t1H, t1L, 2048);
    mma_gemm<0,0><<<dim3(32,1), 256, GEN_SMEM>>>(t1H, t1L, 2048, Wc2H, Wc2L, 2048,
        1024, 32, bc2, dc, nullptr, nullptr, 1024);

    // decoder (persistent, attention fused)
    dec_persist<<<128, 256, DEC_SMEM>>>(dec_b, ba, src_len, out);
}

// round 10
// speedup vs baseline: 1.5058x; 1.4409x over previous
#include <cuda_runtime.h>
#include <cuda_fp16.h>
#include <math.h>
#include <stdint.h>

#define B 128
#define S_SRC 128
#define S_TRG 64
#define H 1024
#define KE 1024
#define KDR 1344
#define KSE 320
#define KAE 576
#define ECH 16
#define DCH 21
#define STGB (160*72*2)                      // A(128) + Wlo(32) rows
#define ENC_SMEM ((ECH*32*72 + 3*160*72)*2)  // 142848
#define DEC_SMEM ((DCH*32*72 + 3*160*72)*2)  // 165888
#define GEN_SMEM 55296                       // A 2x18432 + W 2x9216

// ---------------- weights (fp16 hi/lo, converted once) ----------------
__device__ __half g_WerH[4096*KE],  g_WerL[4096*KE];
__device__ __half g_WdrH[4096*KDR], g_WdrL[4096*KDR];
__device__ __half g_WeiH[4096*KSE], g_WeiL[4096*KSE];
__device__ __half g_WdiH[4096*KAE], g_WdiL[4096*KAE];
__device__ __half g_WqkH[128*1024], g_WqkL[128*1024];
__device__ __half g_WqvH[320*1024], g_WqvL[320*1024];
__device__ __half g_WaH[128*1024],  g_WaL[128*1024];
__device__ __half g_Wh1H[2048*1024], g_Wh1L[2048*1024];
__device__ __half g_Wh2H[1024*2048], g_Wh2L[1024*2048];
__device__ __half g_Wc1H[2048*1024], g_Wc1L[2048*1024];
__device__ __half g_Wc2H[1024*2048], g_Wc2L[1024*2048];

// ---------------- activations / state (fp16 single) ----------------
__device__ __half g_se[(size_t)S_SRC*B*KSE];
__device__ __half g_ae[(size_t)S_TRG*B*KAE];
__device__ float g_encpre[(size_t)S_SRC*B*4096];
__device__ float g_decpre[(size_t)S_TRG*B*4096];
__device__ __half g_sh[(size_t)B*S_SRC*H];
__device__ float g_qkey[(size_t)B*S_SRC*112];
__device__ float g_qval[(size_t)B*S_SRC*304];
__device__ __half g_eh[2*B*H];
__device__ __half g_dA[2*B*KDR];
__device__ float g_ec[B*H], g_dc[B*H];
__device__ __half g_ecA[B*H];
__device__ __half g_t1[B*2048];
__device__ float g_akey[B*112];
__device__ unsigned g_bar1, g_bar2;

#define CP_COMMIT asm volatile("cp.async.commit_group;" ::: "memory")
#define CP_WAIT0  asm volatile("cp.async.wait_group 0;" ::: "memory")
#define CP_WAIT1  asm volatile("cp.async.wait_group 1;" ::: "memory")

__device__ __forceinline__ void ldmx4(uint32_t a, uint32_t* r) {
    asm volatile("ldmatrix.sync.aligned.m8n8.x4.shared.b16 {%0,%1,%2,%3}, [%4];"
                 : "=r"(r[0]),"=r"(r[1]),"=r"(r[2]),"=r"(r[3]) : "r"(a));
}
__device__ __forceinline__ void ldmx2(uint32_t a, uint32_t* r) {
    asm volatile("ldmatrix.sync.aligned.m8n8.x2.shared.b16 {%0,%1}, [%2];"
                 : "=r"(r[0]),"=r"(r[1]) : "r"(a));
}
__device__ __forceinline__ void mma16816(float* c, const uint32_t* a, const uint32_t* b) {
    asm volatile("mma.sync.aligned.m16n8k16.row.col.f32.f16.f16.f32 "
                 "{%0,%1,%2,%3},{%4,%5,%6,%7},{%8,%9},{%0,%1,%2,%3};"
                 : "+f"(c[0]),"+f"(c[1]),"+f"(c[2]),"+f"(c[3])
                 : "r"(a[0]),"r"(a[1]),"r"(a[2]),"r"(a[3]),"r"(b[0]),"r"(b[1]));
}
__device__ __forceinline__ void cpa16(uint32_t d, const void* s) {
    asm volatile("cp.async.cg.shared.global [%0], [%1], 16;" :: "r"(d),"l"(s));
}
__device__ __forceinline__ void grid_sync(unsigned* bar, unsigned target) {
    __syncthreads();
    if (threadIdx.x == 0) {
        __threadfence();
        atomicAdd(bar, 1u);
        volatile unsigned* vb = (volatile unsigned*)bar;
        while (*vb < target) __nanosleep(64);
        __threadfence();
    }
    __syncthreads();
}

// ---- setup: fp32 -> fp16 hi/lo (dl may be null -> single) ----
__global__ void convw_kernel(__half* dh, __half* dl,
                             const float* __restrict__ s1, const float* __restrict__ s2,
                             int Npad, int Nreal, int Kpad, int Kreal, int lds, int mode) {
    int64_t tot = (int64_t)Npad * Kpad;
    int64_t stride = (int64_t)gridDim.x * blockDim.x;
    for (int64_t i = (int64_t)blockIdx.x*blockDim.x + threadIdx.x; i < tot; i += stride) {
        int n = (int)(i / Kpad), k = (int)(i % Kpad);
        float v = 0.f;
        if (mode == 0) { if (n < Nreal && k < Kreal) v = s1[(int64_t)n*lds + k]; }
        else {
            int orig = (n & 3)*1024 + (n >> 2);
            if (mode == 1) { if (k < Kreal) v = s1[(int64_t)orig*lds + k]; }
            else {
                if (k < 1024) v = s1[(int64_t)orig*1024 + k];
                else if (k < 1324) v = s2[(int64_t)orig*856 + 556 + (k-1024)];
            }
        }
        __half hv = __float2half(v);
        dh[i] = hv;
        if (dl) dl[i] = __float2half(v - __half2float(hv));
    }
}

__global__ void gather_kernel(const int* __restrict__ src_seqs, const int* __restrict__ trg_nt,
                              const int* __restrict__ par_nt, const int* __restrict__ par_lex,
                              const float* __restrict__ lex_emb, const float* __restrict__ nt_emb) {
    if (blockIdx.x == 0 && threadIdx.x == 0) { g_bar1 = 0u; g_bar2 = 0u; }
    const int64_t nse = (int64_t)S_SRC*B*KSE;
    const int64_t nae = (int64_t)S_TRG*B*KAE;
    int64_t stride = (int64_t)gridDim.x * blockDim.x;
    __half z16 = __float2half(0.f);
    for (int64_t i = (int64_t)blockIdx.x*blockDim.x + threadIdx.x; i < nse; i += stride) {
        {
            int d = (int)(i % KSE), r = (int)(i / KSE);
            int s = r >> 7, b = r & 127;
            float v = (d < 300) ? lex_emb[(int64_t)src_seqs[b*S_SRC+s]*300 + d] : 0.f;
            g_se[i] = __float2half(v);
        }
        if (i < nae) {
            int d = (int)(i % KAE), r = (int)(i / KAE);
            int t = r >> 7, b = r & 127;
            float v = 0.f;
            if (d < 128)      v = nt_emb[(int64_t)trg_nt[b*S_TRG+t]*128 + d];
            else if (d < 256) v = nt_emb[(int64_t)par_nt[b*S_TRG+t]*128 + (d-128)];
            else if (d < 556) v = lex_emb[(int64_t)par_lex[b*S_TRG+t]*300 + (d-256)];
            g_ae[i] = __float2half(v);
        }
        if (i < 2*B*KDR) g_dA[i] = z16;
        if (i < 2*B*H)   g_eh[i] = z16;
        if (i < B*H)     g_ec[i] = 0.f;
    }
}

// ============ persistent recurrence machinery ============
// stage rows(72 fp16): 0..127 A, 128..159 W_lo
__device__ __forceinline__ void stream_chunk(uint32_t st, int t, int k0,
    const __half* __restrict__ A, int ldA,
    const __half* __restrict__ Wl, int ldW, int nbase)
{
#pragma unroll
    for (int i = 0; i < 5; i++) {
        int u = i*256 + t;
        int row = u >> 3, grp = u & 7;
        const __half* src;
        if (row < 128) src = A + (int64_t)row*ldA + k0 + grp*8;
        else           src = Wl + (int64_t)(nbase + row - 128)*ldW + k0 + grp*8;
        cpa16(st + (uint32_t)(row*72 + grp*8)*2u, src);
    }
    CP_COMMIT;
}

template<int KCH>
__device__ __forceinline__ void load_resident(uint32_t smW, int t,
    const __half* __restrict__ Whg, int ldW, int nbase)
{
    int rr = (t >> 3) & 31, grp = t & 7;
#pragma unroll
    for (int i = 0; i < KCH; i++)
        cpa16(smW + (uint32_t)((i*32 + rr)*72 + grp*8)*2u,
              Whg + (int64_t)(nbase + rr)*ldW + i*64 + grp*8);
    CP_COMMIT; CP_WAIT0;
    __syncthreads();
}

__device__ __forceinline__ void mma_chunk(uint32_t smWc, uint32_t st,
    int lane, int wm, int wn, float acc[2][2][4])
{
#pragma unroll
    for (int kk16 = 0; kk16 < 64; kk16 += 16) {
        uint32_t bh[2][2], bl[2][2];
#pragma unroll
        for (int nf = 0; nf < 2; nf++) {
            int rowW = wn*16 + nf*8 + (lane & 7);
            int kcol = kk16 + ((lane >> 3) & 1)*8;
            ldmx2(smWc + (uint32_t)(rowW*72 + kcol)*2u, bh[nf]);
            ldmx2(st + (uint32_t)((128 + rowW)*72 + kcol)*2u, bl[nf]);
        }
#pragma unroll
        for (int mf = 0; mf < 2; mf++) {
            int rowA = wm*32 + mf*16 + (lane & 7) + ((lane >> 3) & 1)*8;
            int kcol = kk16 + ((lane >> 4) & 1)*8;
            uint32_t a4[4];
            ldmx4(st + (uint32_t)(rowA*72 + kcol)*2u, a4);
#pragma unroll
            for (int nf = 0; nf < 2; nf++) {
                mma16816(acc[mf][nf], a4, bh[nf]);
                mma16816(acc[mf][nf], a4, bl[nf]);
            }
        }
    }
}

template<int KCH>
__device__ __forceinline__ void gemm_phase(uint32_t smW, uint32_t smS, int t, int lane,
    int wm, int wn,
    const __half* __restrict__ A, int ldA,
    const __half* __restrict__ Wlg, int ldW, int nbase, float acc[2][2][4])
{
    stream_chunk(smS, t, 0, A, ldA, Wlg, ldW, nbase);
    stream_chunk(smS + STGB, t, 64, A, ldA, Wlg, ldW, nbase);
    for (int c = 0; c < KCH; c++) {
        if (c < KCH - 1) { CP_WAIT1; } else { CP_WAIT0; }
        __syncthreads();
        if (c + 2 < KCH)
            stream_chunk(smS + ((c+2)%3)*STGB, t, (c+2)*64, A, ldA, Wlg, ldW, nbase);
        mma_chunk(smW + (uint32_t)c*(32*72*2), smS + (c%3)*STGB, lane, wm, wn, acc);
    }
    __syncthreads();
}

// ---------------- persistent encoder ----------------
__global__ __launch_bounds__(256) void enc_persist(const float* __restrict__ biasv,
                                                   const int* __restrict__ lens) {
    extern __shared__ char smraw[];
    const uint32_t smb = (uint32_t)__cvta_generic_to_shared(smraw);
    const uint32_t smW = smb;
    const uint32_t smS = smb + (uint32_t)(ECH*32*72*2);
    const int t = threadIdx.x;
    const int lane = t & 31, w = t >> 5;
    const int wm = w & 3, wn = w >> 2;
    const int nbase = blockIdx.x*32;
    const int g2 = lane >> 2, q2 = (lane & 3)*2;

    load_resident<ECH>(smW, t, g_WerH, KE, nbase);

    unsigned target = 0;
    for (int s = 0; s < S_SRC; s++) {
        const int p = s & 1;
        const __half* Ah = g_eh + p*B*H;
        __half* Ho = g_eh + (p^1)*B*H;
        const float* add = g_encpre + (int64_t)s*B*4096;

        float acc[2][2][4];
#pragma unroll
        for (int a = 0; a < 2; a++)
#pragma unroll
            for (int b2 = 0; b2 < 2; b2++)
#pragma unroll
                for (int r = 0; r < 4; r++) acc[a][b2][r] = 0.f;

        gemm_phase<ECH>(smW, smS, t, lane, wm, wn, Ah, H, g_WerL, KE, nbase, acc);

        float* zb = (float*)(smraw + ECH*32*72*2);
#pragma unroll
        for (int mf = 0; mf < 2; mf++)
#pragma unroll
            for (int nf = 0; nf < 2; nf++)
#pragma unroll
                for (int r = 0; r < 4; r++) {
                    int row = wm*32 + mf*16 + g2 + (r >> 1)*8;
                    int col = wn*16 + nf*8 + q2 + (r & 1);
                    zb[row*33 + col] = acc[mf][nf][r];
                }
        __syncthreads();

        const int b = t & 127;
        const int jj0 = (t >> 7)*4;
        bool valid = s < lens[b];
        __half z16 = __float2half(0.f);
#pragma unroll
        for (int jj = jj0; jj < jj0 + 4; jj++) {
            int jglob = (nbase >> 2) + jj;
            float4 pre = *(const float4*)&add[(int64_t)b*4096 + nbase + jj*4];
            float zi = zb[b*33 + jj*4 + 0] + pre.x + biasv[jglob];
            float zf = zb[b*33 + jj*4 + 1] + pre.y + biasv[1024 + jglob];
            float zg = zb[b*33 + jj*4 + 2] + pre.z + biasv[2048 + jglob];
            float zo = zb[b*33 + jj*4 + 3] + pre.w + biasv[3072 + jglob];
            float cold = g_ec[b*H + jglob];
            float si = 1.f/(1.f + expf(-zi));
            float sf = 1.f/(1.f + expf(-zf));
            float so = 1.f/(1.f + expf(-zo));
            float c2 = sf*cold + si*tanhf(zg);
            float h2 = so*tanhf(c2);
            if (valid) g_ec[b*H + jglob] = c2;
            __half nh = __float2half(h2);
            Ho[b*H + jglob] = valid ? nh : Ah[b*H + jglob];
            g_sh[((int64_t)b*S_SRC + s)*H + jglob] = valid ? nh : z16;
        }
        grid_sync(&g_bar1, target += 128);
    }
}

// ---------------- persistent decoder ----------------
// mini stage rows: 0..127 A, 128..135 Wa_hi, 136..143 Wa_lo
__device__ __forceinline__ void stream_mini(uint32_t st, int t, int k0,
    const __half* __restrict__ A, int nb8)
{
#pragma unroll
    for (int i = 0; i < 5; i++) {
        int u = i*256 + t;
        if (u >= 1152) break;
        int row = u >> 3, grp = u & 7;
        const __half* src;
        if (row < 128)      src = A + (int64_t)row*KDR + k0 + grp*8;
        else if (row < 136) src = g_WaH + (int64_t)(nb8 + row - 128)*1024 + k0 + grp*8;
        else                src = g_WaL + (int64_t)(nb8 + row - 136)*1024 + k0 + grp*8;
        cpa16(st + (uint32_t)(row*72 + grp*8)*2u, src);
    }
    CP_COMMIT;
}

__global__ __launch_bounds__(256) void dec_persist(const float* __restrict__ biasv,
                                                   const float* __restrict__ ba_,
                                                   const int* __restrict__ lens,
                                                   float* __restrict__ outF) {
    extern __shared__ char smraw[];
    __shared__ float s_ak[112];
    __shared__ float s_en[128];
    __shared__ float s_red[8];
    const uint32_t smb = (uint32_t)__cvta_generic_to_shared(smraw);
    const uint32_t smW = smb;
    const uint32_t smS = smb + (uint32_t)(DCH*32*72*2);
    const int t = threadIdx.x;
    const int lane = t & 31, w = t >> 5;
    const int wm = w & 3, wn = w >> 2;
    const int nbase = blockIdx.x*32;
    const int g2 = lane >> 2, q2 = (lane & 3)*2;
    const int myb = blockIdx.x;

    load_resident<DCH>(smW, t, g_WdrH, KDR, nbase);

    unsigned target = 0;
    for (int ts = 0; ts < S_TRG; ts++) {
        const int p = ts & 1;
        __half* dAp = g_dA + p*B*KDR;
        __half* nAp = g_dA + (p^1)*B*KDR;

        // A1: a_key mini-GEMM (blocks 0..13, N=8)
        if (blockIdx.x < 14) {
            const int nb8 = blockIdx.x*8;
            float acm[4] = {0.f,0.f,0.f,0.f};
            stream_mini(smS, t, 0, dAp, nb8);
            for (int c = 0; c < 16; c++) {
                if (c < 15) stream_mini(smS + ((c+1)&1)*STGB, t, (c+1)*64, dAp, nb8);
                if (c < 15) { CP_WAIT1; } else { CP_WAIT0; }
                __syncthreads();
                uint32_t st = smS + (c & 1)*STGB;
#pragma unroll
                for (int kk16 = 0; kk16 < 64; kk16 += 16) {
                    uint32_t bh[2], bl[2];
                    int rowW = lane & 7;
                    int kcolW = kk16 + ((lane >> 3) & 1)*8;
                    ldmx2(st + (uint32_t)((128 + rowW)*72 + kcolW)*2u, bh);
                    ldmx2(st + (uint32_t)((136 + rowW)*72 + kcolW)*2u, bl);
                    int rowA = w*16 + (lane & 7) + ((lane >> 3) & 1)*8;
                    int kcolA = kk16 + ((lane >> 4) & 1)*8;
                    uint32_t a4[4];
                    ldmx4(st + (uint32_t)(rowA*72 + kcolA)*2u, a4);
                    mma16816(acm, a4, bh);
                    mma16816(acm, a4, bl);
                }
                __syncthreads();
            }
#pragma unroll
            for (int r = 0; r < 4; r++) {
                int row = w*16 + g2 + (r >> 1)*8;
                int gc = nb8 + q2 + (r & 1);
                float bb = (gc < 100) ? ba_[gc] : 0.f;
                g_akey[row*112 + gc] = tanhf(acm[r] + bb);
            }
        }
        grid_sync(&g_bar2, target += 128);

        // A2: softmax + context for batch myb
        {
            if (t < 112) s_ak[t] = g_akey[myb*112 + t];
            __syncthreads();
            float ex = 0.f;
            if (t < 128) {
                int L = lens[myb];
                const float* qk = g_qkey + ((int64_t)myb*S_SRC + t)*112;
                float pp = 0.f;
#pragma unroll 4
                for (int d = 0; d < 100; d++) pp = fmaf(qk[d], s_ak[d], pp);
                float e = (t < L) ? pp : -1e9f;
                float mx = e;
                for (int o = 16; o; o >>= 1) mx = fmaxf(mx, __shfl_xor_sync(0xffffffffu, mx, o));
                if (lane == 0) s_red[w] = mx;
                s_en[t] = e;
            }
            __syncthreads();
            if (t < 128) {
                float mx = fmaxf(fmaxf(s_red[0], s_red[1]), fmaxf(s_red[2], s_red[3]));
                ex = expf(s_en[t] - mx);
                float sm = ex;
                for (int o = 16; o; o >>= 1) sm += __shfl_xor_sync(0xffffffffu, sm, o);
                if (lane == 0) s_red[4 + w] = sm;
            }
            __syncthreads();
            if (t < 128) s_en[t] = ex;
            __syncthreads();
            float denom = s_red[4] + s_red[5] + s_red[6] + s_red[7];
            for (int d = t; d < 300; d += 256) {
                float c = 0.f;
#pragma unroll 4
                for (int s2 = 0; s2 < S_SRC; s2++)
                    c = fmaf(s_en[s2], g_qval[((int64_t)myb*S_SRC + s2)*304 + d], c);
                c /= denom;
                dAp[(int64_t)myb*KDR + 1024 + d] = __float2half(c);
            }
        }
        grid_sync(&g_bar2, target += 128);

        // B: recurrent GEMM + LSTM epilogue
        {
            const float* add = g_decpre + (int64_t)ts*B*4096;
            float acc[2][2][4];
#pragma unroll
            for (int a = 0; a < 2; a++)
#pragma unroll
                for (int b2 = 0; b2 < 2; b2++)
#pragma unroll
                    for (int r = 0; r < 4; r++) acc[a][b2][r] = 0.f;

            gemm_phase<DCH>(smW, smS, t, lane, wm, wn, dAp, KDR, g_WdrL, KDR, nbase, acc);

            float* zb = (float*)(smraw + DCH*32*72*2);
#pragma unroll
            for (int mf = 0; mf < 2; mf++)
#pragma unroll
                for (int nf = 0; nf < 2; nf++)
#pragma unroll
                    for (int r = 0; r < 4; r++) {
                        int row = wm*32 + mf*16 + g2 + (r >> 1)*8;
                        int col = wn*16 + nf*8 + q2 + (r & 1);
                        zb[row*33 + col] = acc[mf][nf][r];
                    }
            __syncthreads();

            const int b = t & 127;
            const int jj0 = (t >> 7)*4;
#pragma unroll
            for (int jj = jj0; jj < jj0 + 4; jj++) {
                int jglob = (nbase >> 2) + jj;
                float4 pre = *(const float4*)&add[(int64_t)b*4096 + nbase + jj*4];
                float zi = zb[b*33 + jj*4 + 0] + pre.x + biasv[jglob];
                float zf = zb[b*33 + jj*4 + 1] + pre.y + biasv[1024 + jglob];
                float zg = zb[b*33 + jj*4 + 2] + pre.z + biasv[2048 + jglob];
                float zo = zb[b*33 + jj*4 + 3] + pre.w + biasv[3072 + jglob];
                float cold = g_dc[b*H + jglob];
                float si = 1.f/(1.f + expf(-zi));
                float sf = 1.f/(1.f + expf(-zf));
                float so = 1.f/(1.f + expf(-zo));
                float c2 = sf*cold + si*tanhf(zg);
                float h2 = so*tanhf(c2);
                g_dc[b*H + jglob] = c2;
                nAp[(int64_t)b*KDR + jglob] = __float2half(h2);
                outF[((int64_t)b*S_TRG + ts)*H + jglob] = h2;
            }
        }
        grid_sync(&g_bar2, target += 128);
    }
}

// ---------------- one-shot GEMM (A single fp16, W hi/lo, 2-pass) ----------------
// smem: A[buf][128][72] at buf*18432; W[buf][hl][32][72] at 36864
__device__ __forceinline__ void load_chunk_g(uint32_t smb, int buf, int t, int k0,
    const __half* __restrict__ A, int ldA, int mbase,
    const __half* __restrict__ Wh, const __half* __restrict__ Wl, int ldW, int nbase)
{
#pragma unroll
    for (int i = 0; i < 4; i++) {
        int u = i*256 + t;
        int row = u >> 3, grp = u & 7;
        const __half* src = A + (int64_t)(mbase + row)*ldA + k0 + grp*8;
        cpa16(smb + (uint32_t)buf*18432u + (uint32_t)(row*72 + grp*8)*2u, src);
    }
#pragma unroll
    for (int i = 0; i < 2; i++) {
        int u = i*256 + t;
        int hl = u >> 8, rem = u & 255;
        int row = rem >> 3, grp = rem & 7;
        const __half* src = (hl ? Wl : Wh) + (int64_t)(nbase + row)*ldW + k0 + grp*8;
        cpa16(smb + 36864u + (uint32_t)(((buf*2 + hl)*32 + row)*72 + grp*8)*2u, src);
    }
    CP_COMMIT;
}

template<int OUT, int ACT>   // OUT: 0 fp32, 1 fp16 ; ACT: 0 none, 1 relu, 2 tanh
__global__ __launch_bounds__(256) void mma_gemm(
    const __half* __restrict__ A, int ldA,
    const __half* __restrict__ Wh, const __half* __restrict__ Wl, int ldW,
    int N, int KT, const float* __restrict__ bias,
    float* __restrict__ Cf, __half* __restrict__ Ch, int ldC)
{
    extern __shared__ char smraw[];
    uint32_t smb = (uint32_t)__cvta_generic_to_shared(smraw);
    const int t = threadIdx.x;
    const int lane = t & 31, w = t >> 5;
    const int wm = w & 3, wn = w >> 2;
    const int mbase = blockIdx.y*128;
    const int nbase = blockIdx.x*32;

    float acc[2][2][4];
#pragma unroll
    for (int a = 0; a < 2; a++)
#pragma unroll
        for (int b2 = 0; b2 < 2; b2++)
#pragma unroll
            for (int r = 0; r < 4; r++) acc[a][b2][r] = 0.f;

    load_chunk_g(smb, 0, t, 0, A, ldA, mbase, Wh, Wl, ldW, nbase);

    for (int kc = 0; kc < KT; kc++) {
        const int cur = kc & 1;
        if (kc + 1 < KT) {
            load_chunk_g(smb, cur ^ 1, t, (kc+1)*64, A, ldA, mbase, Wh, Wl, ldW, nbase);
            CP_WAIT1;
        } else { CP_WAIT0; }
        __syncthreads();
#pragma unroll
        for (int kk16 = 0; kk16 < 64; kk16 += 16) {
            uint32_t bh[2][2], bl[2][2];
#pragma unroll
            for (int nf = 0; nf < 2; nf++) {
                int rowW = wn*16 + nf*8 + (lane & 7);
                int kcol = kk16 + ((lane >> 3) & 1)*8;
                ldmx2(smb + 36864u + (uint32_t)(((cur*2+0)*32 + rowW)*72 + kcol)*2u, bh[nf]);
                ldmx2(smb + 36864u + (uint32_t)(((cur*2+1)*32 + rowW)*72 + kcol)*2u, bl[nf]);
            }
#pragma unroll
            for (int mf = 0; mf < 2; mf++) {
                int rowA = wm*32 + mf*16 + (lane & 7) + ((lane >> 3) & 1)*8;
                int kcol = kk16 + ((lane >> 4) & 1)*8;
                uint32_t a4[4];
                ldmx4(smb + (uint32_t)cur*18432u + (uint32_t)(rowA*72 + kcol)*2u, a4);
#pragma unroll
                for (int nf = 0; nf < 2; nf++) {
                    mma16816(acc[mf][nf], a4, bh[nf]);
                    mma16816(acc[mf][nf], a4, bl[nf]);
                }
            }
        }
        __syncthreads();
    }

    const int g2 = lane >> 2, q2 = (lane & 3)*2;
#pragma unroll
    for (int mf = 0; mf < 2; mf++)
#pragma unroll
        for (int nf = 0; nf < 2; nf++)
#pragma unroll
            for (int r = 0; r < 4; r++) {
                int row = mbase + wm*32 + mf*16 + g2 + (r >> 1)*8;
                int col = nbase + wn*16 + nf*8 + q2 + (r & 1);
                if (col < N) {
                    float v = acc[mf][nf][r];
                    if (bias) v += bias[col];
                    if (ACT == 1) v = fmaxf(v, 0.f);
                    if (ACT == 2) v = tanhf(v);
                    if (OUT == 0) Cf[(int64_t)row*ldC + col] = v;
                    else Ch[(int64_t)row*ldC + col] = __float2half(v);
                }
            }
}

// ---------------- launcher ----------------
#define GSA(p, s) cudaGetSymbolAddress((void**)&p, s)

extern "C" void kernel_launch(void* const* d_in, const int* in_sizes, int n_in,
                              void* d_out, int out_size) {
    const int* src_seqs = (const int*)d_in[0];
    const int* src_len = (const int*)d_in[1];
    const int* trg_nt = (const int*)d_in[2];
    const int* par_nt = (const int*)d_in[3];
    const int* par_lex = (const int*)d_in[4];
    const float* lex_emb = (const float*)d_in[5];
    const float* nt_emb = (const float*)d_in[6];
    const float* enc_Wih = (const float*)d_in[7];
    const float* enc_Whh = (const float*)d_in[8];
    const float* enc_b = (const float*)d_in[9];
    const float* dec_Wih = (const float*)d_in[10];
    const float* dec_Whh = (const float*)d_in[11];
    const float* dec_b = (const float*)d_in[12];
    const float* Wh1 = (const float*)d_in[13];
    const float* bh1 = (const float*)d_in[14];
    const float* Wh2 = (const float*)d_in[15];
    const float* bh2 = (const float*)d_in[16];
    const float* Wc1 = (const float*)d_in[17];
    const float* bc1 = (const float*)d_in[18];
    const float* Wc2 = (const float*)d_in[19];
    const float* bc2 = (const float*)d_in[20];
    const float* Wa = (const float*)d_in[21];
    const float* ba = (const float*)d_in[22];
    const float* Wqk = (const float*)d_in[23];
    const float* bqk = (const float*)d_in[24];
    const float* Wqv = (const float*)d_in[25];
    const float* bqv = (const float*)d_in[26];
    float* out = (float*)d_out;

    cudaFuncSetAttribute(mma_gemm<0,0>, cudaFuncAttributeMaxDynamicSharedMemorySize, GEN_SMEM);
    cudaFuncSetAttribute(mma_gemm<0,2>, cudaFuncAttributeMaxDynamicSharedMemorySize, GEN_SMEM);
    cudaFuncSetAttribute(mma_gemm<1,0>, cudaFuncAttributeMaxDynamicSharedMemorySize, GEN_SMEM);
    cudaFuncSetAttribute(mma_gemm<1,1>, cudaFuncAttributeMaxDynamicSharedMemorySize, GEN_SMEM);
    cudaFuncSetAttribute(enc_persist, cudaFuncAttributeMaxDynamicSharedMemorySize, ENC_SMEM);
    cudaFuncSetAttribute(dec_persist, cudaFuncAttributeMaxDynamicSharedMemorySize, DEC_SMEM);

    __half *WerH,*WerL,*WdrH,*WdrL,*WeiH,*WeiL,*WdiH,*WdiL;
    __half *WqkH,*WqkL,*WqvH,*WqvL,*WaH,*WaL;
    __half *Wh1H,*Wh1L,*Wh2H,*Wh2L,*Wc1H,*Wc1L,*Wc2H,*Wc2L;
    __half *se,*ae,*sh,*eh,*dA,*ecA,*t1;
    float *encpre,*decpre,*qkey,*qval,*ec,*dc;
    GSA(WerH,g_WerH); GSA(WerL,g_WerL); GSA(WdrH,g_WdrH); GSA(WdrL,g_WdrL);
    GSA(WeiH,g_WeiH); GSA(WeiL,g_WeiL); GSA(WdiH,g_WdiH); GSA(WdiL,g_WdiL);
    GSA(WqkH,g_WqkH); GSA(WqkL,g_WqkL); GSA(WqvH,g_WqvH); GSA(WqvL,g_WqvL);
    GSA(WaH,g_WaH);   GSA(WaL,g_WaL);
    GSA(Wh1H,g_Wh1H); GSA(Wh1L,g_Wh1L); GSA(Wh2H,g_Wh2H); GSA(Wh2L,g_Wh2L);
    GSA(Wc1H,g_Wc1H); GSA(Wc1L,g_Wc1L); GSA(Wc2H,g_Wc2H); GSA(Wc2L,g_Wc2L);
    GSA(se,g_se); GSA(ae,g_ae); GSA(sh,g_sh); GSA(eh,g_eh); GSA(dA,g_dA);
    GSA(ecA,g_ecA); GSA(t1,g_t1);
    GSA(encpre,g_encpre); GSA(decpre,g_decpre);
    GSA(qkey,g_qkey); GSA(qval,g_qval); GSA(ec,g_ec); GSA(dc,g_dc);

    // L0..L4: encoder deps
    convw_kernel<<<1024, 256>>>(WerH, WerL, enc_Whh, nullptr, 4096, 0, KE, 1024, 1024, 1);
    convw_kernel<<<1024, 256>>>(WeiH, WeiL, enc_Wih, nullptr, 4096, 0, KSE, 300, 300, 1);
    gather_kernel<<<2048, 256>>>(src_seqs, trg_nt, par_nt, par_lex, lex_emb, nt_emb);
    mma_gemm<0,0><<<dim3(128,128), 256, GEN_SMEM>>>(se, KSE, WeiH, WeiL, KSE,
        4096, KSE/64, nullptr, encpre, nullptr, 4096);
    convw_kernel<<<1024, 256>>>(WdrH, WdrL, dec_Whh, dec_Wih, 4096, 0, KDR, 1324, 0, 2);

    // L5: encoder persistent (profiling target)
    enc_persist<<<128, 256, ENC_SMEM>>>(enc_b, src_len);

    // remaining setup
    convw_kernel<<<1024, 256>>>(WdiH, WdiL, dec_Wih, nullptr, 4096, 0, KAE, 556, 856, 1);
    convw_kernel<<<256, 256>>>(WqkH, WqkL, Wqk, nullptr, 128, 100, 1024, 1024, 1024, 0);
    convw_kernel<<<256, 256>>>(WqvH, WqvL, Wqv, nullptr, 320, 300, 1024, 1024, 1024, 0);
    convw_kernel<<<256, 256>>>(WaH,  WaL,  Wa,  nullptr, 128, 100, 1024, 1024, 1024, 0);
    convw_kernel<<<1024, 256>>>(Wh1H, Wh1L, Wh1, nullptr, 2048, 2048, 1024, 1024, 1024, 0);
    convw_kernel<<<1024, 256>>>(Wh2H, Wh2L, Wh2, nullptr, 1024, 1024, 2048, 2048, 2048, 0);
    convw_kernel<<<1024, 256>>>(Wc1H, Wc1L, Wc1, nullptr, 2048, 2048, 1024, 1024, 1024, 0);
    convw_kernel<<<1024, 256>>>(Wc2H, Wc2L, Wc2, nullptr, 1024, 1024, 2048, 2048, 2048, 0);

    // dec input precompute
    mma_gemm<0,0><<<dim3(128,64), 256, GEN_SMEM>>>(ae, KAE, WdiH, WdiL, KAE,
        4096, KAE/64, nullptr, decpre, nullptr, 4096);

    // attention keys/values
    mma_gemm<0,2><<<dim3(4,128), 256, GEN_SMEM>>>(sh, H, WqkH, WqkL, 1024,
        100, 16, bqk, qkey, nullptr, 112);
    mma_gemm<0,0><<<dim3(10,128), 256, GEN_SMEM>>>(sh, H, WqvH, WqvL, 1024,
        300, 16, bqv, qval, nullptr, 304);

    // decoder init MLPs (final enc h in buffer 0 of g_eh)
    convw_kernel<<<256, 256>>>(ecA, nullptr, ec, nullptr, 128, 128, 1024, 1024, 1024, 0);
    mma_gemm<1,1><<<dim3(64,1), 256, GEN_SMEM>>>(eh, H, Wh1H, Wh1L, 1024,
        2048, 16, bh1, nullptr, t1, 2048);
    mma_gemm<1,0><<<dim3(32,1), 256, GEN_SMEM>>>(t1, 2048, Wh2H, Wh2L, 2048,
        1024, 32, bh2, nullptr, dA, KDR);
    mma_gemm<1,1><<<dim3(64,1), 256, GEN_SMEM>>>(ecA, H, Wc1H, Wc1L, 1024,
        2048, 16, bc1, nullptr, t1, 2048);
    mma_gemm<0,0><<<dim3(32,1), 256, GEN_SMEM>>>(t1, 2048, Wc2H, Wc2L, 2048,
        1024, 32, bc2, dc, nullptr, 1024);

    // decoder persistent
    dec_persist<<<128, 256, DEC_SMEM>>>(dec_b, ba, src_len, out);
}